// round 8
// baseline (speedup 1.0000x reference)
#include <cuda_runtime.h>
#include <cuda_bf16.h>
#include <cuda_pipeline.h>
#include <math.h>
#include <stdint.h>

#define BB 4
#define TT 2048
#define DD 512
#define HH 2048
#define VV 256
#define NTOK (BB*TT)   // 8192
#define CS 64
#define NCH (TT/CS)

// ---------------- scratch ----------------
__device__ __align__(128) float g_h[NTOK*DD];
__device__ __align__(128) float g_s1[NTOK*DD];
__device__ __align__(128) float g_partA[BB*NCH*DD];
__device__ __align__(128) float g_partB[BB*NCH*DD];
__device__ __align__(128) __nv_bfloat16 g_s2h[NTOK*DD];
__device__ __align__(128) __nv_bfloat16 g_s2l[NTOK*DD];
__device__ __align__(128) __nv_bfloat16 g_acth[(size_t)NTOK*HH];
__device__ __align__(128) __nv_bfloat16 g_actl[(size_t)NTOK*HH];
__device__ __align__(128) __nv_bfloat16 g_w1h[3*DD*HH];
__device__ __align__(128) __nv_bfloat16 g_w1l[3*DD*HH];
__device__ __align__(128) __nv_bfloat16 g_w2h[3*DD*HH];
__device__ __align__(128) __nv_bfloat16 g_w2l[3*DD*HH];

__device__ __forceinline__ float softplus_lambda(float kv) {
    float sp = (kv > 0.f) ? (kv + log1pf(expf(-kv))) : log1pf(expf(kv));
    return expf(-sp);
}

// ---------------- weight split prepass (bf16 hi/lo) ----------------
__global__ void split_weights_kernel(const float* __restrict__ W1, const float* __restrict__ W2) {
    size_t i = (size_t)blockIdx.x * blockDim.x + threadIdx.x;
    float v1 = W1[i];
    __nv_bfloat16 h1 = __float2bfloat16(v1);
    g_w1h[i] = h1;
    g_w1l[i] = __float2bfloat16(v1 - __bfloat162float(h1));
    float v2 = W2[i];
    __nv_bfloat16 h2 = __float2bfloat16(v2);
    g_w2h[i] = h2;
    g_w2l[i] = __float2bfloat16(v2 - __bfloat162float(h2));
}

// ---------------- fused embed gather + tanh(cumprod) (warp per token) ------
__global__ void embed_cumprod_kernel(const int* __restrict__ x, const float* __restrict__ embed) {
    int w = threadIdx.x >> 5;
    int lane = threadIdx.x & 31;
    int tok = blockIdx.x * 8 + w;
    const float* src = embed + (size_t)x[tok] * DD;
    size_t base = (size_t)tok * DD + lane * 16;
    float v[16];
    #pragma unroll
    for (int j = 0; j < 4; j++)
        *(float4*)&v[j * 4] = *(const float4*)(src + lane * 16 + j * 4);
    float c[16];
    float run = 1.f;
    #pragma unroll
    for (int j = 0; j < 16; j++) {
        run *= v[j];
        c[j] = run;
    }
    float incl = run;
    #pragma unroll
    for (int off = 1; off < 32; off <<= 1) {
        float p = __shfl_up_sync(0xffffffffu, incl, off);
        if (lane >= off) incl *= p;
    }
    float pre = __shfl_up_sync(0xffffffffu, incl, 1);
    if (lane == 0) pre = 1.f;
    #pragma unroll
    for (int j = 0; j < 4; j++) {
        *(float4*)&g_h[base + j * 4] = *(const float4*)&v[j * 4];
        float4 o;
        o.x = tanhf(pre * c[j * 4 + 0]);
        o.y = tanhf(pre * c[j * 4 + 1]);
        o.z = tanhf(pre * c[j * 4 + 2]);
        o.w = tanhf(pre * c[j * 4 + 3]);
        *(float4*)&g_s1[base + j * 4] = o;
    }
}

// ============= boundary scan ================================================
__global__ void boundA_kernel() {
    int b = blockIdx.x, ch = blockIdx.y, d = threadIdx.x;
    size_t base = ((size_t)b * TT + ch * CS) * DD + d;
    float s = 0.f;
    #pragma unroll 8
    for (int i = 0; i < CS; i++) s += g_s1[base + (size_t)i * DD];
    g_partA[((size_t)b * NCH + ch) * DD + d] = s;
}

__global__ void boundB_kernel() {
    int b = blockIdx.x, d = threadIdx.x;
    float c = 0.f;
    for (int ch = 0; ch < NCH; ch++) {
        size_t idx = ((size_t)b * NCH + ch) * DD + d;
        float v = g_partA[idx];
        g_partA[idx] = c;
        c += v;
    }
}

__global__ void boundC_kernel() {
    int b = blockIdx.x, ch = blockIdx.y, d = threadIdx.x;
    size_t base = ((size_t)b * TT + ch * CS) * DD + d;
    float acc = g_partA[((size_t)b * NCH + ch) * DD + d];
    #pragma unroll 4
    for (int i = 0; i < CS; i++) {
        size_t idx = base + (size_t)i * DD;
        acc += g_s1[idx];
        g_h[idx] = g_h[idx] * (1.0f + acc);
    }
}

// ============= per-layer scans =============================================
__global__ void scanA_kernel(const float* __restrict__ kpar, int l) {
    int b = blockIdx.x, ch = blockIdx.y, d = threadIdx.x;
    float lam = softplus_lambda(kpar[l]);
    size_t base = ((size_t)b * TT + ch * CS) * DD + d;
    float s = 0.f, loc = 0.f;
    #pragma unroll 4
    for (int i = 0; i < CS; i++) {
        float v = g_h[base + (size_t)i * DD];
        s += v;
        loc = v + lam * loc;
    }
    size_t pidx = ((size_t)b * NCH + ch) * DD + d;
    g_partA[pidx] = s;
    g_partB[pidx] = loc;
}

__global__ void scanB_kernel(const float* __restrict__ kpar, int l) {
    int b = blockIdx.x, d = threadIdx.x;
    float lam = softplus_lambda(kpar[l]);
    float lamCS = powf(lam, (float)CS);
    float c1 = 0.f, c2 = 0.f;
    for (int ch = 0; ch < NCH; ch++) {
        size_t idx = ((size_t)b * NCH + ch) * DD + d;
        float a = g_partA[idx];
        float v = g_partB[idx];
        g_partA[idx] = c1;
        g_partB[idx] = c2;
        c1 += a;
        c2 = v + lamCS * c2;
    }
}

// ======== fused mag + decay-ctx ============================================
__global__ void magdecayC_kernel(const float* __restrict__ kpar, int l) {
    __shared__ float accw[CS][17];
    __shared__ float smag[CS];
    int b = blockIdx.x, ch = blockIdx.y;
    int d = threadIdx.x;
    int lane = d & 31, wid = d >> 5;
    int t0 = ch * CS;
    size_t base = ((size_t)b * TT + t0) * DD + d;
    float acc = g_partA[((size_t)b * NCH + ch) * DD + d];
    float hp = (t0 > 0) ? g_h[base - DD] : 0.f;
    #pragma unroll 4
    for (int i = 0; i < CS; i++) {
        float v = g_h[base + (size_t)i * DD];
        acc += v;
        float diff = acc - hp;
        float sq = diff * diff;
        #pragma unroll
        for (int o = 16; o; o >>= 1) sq += __shfl_down_sync(0xffffffffu, sq, o);
        if (lane == 0) accw[i][wid] = sq;
        hp = v;
    }
    __syncthreads();
    if (d < CS) {
        float s = 0.f;
        #pragma unroll
        for (int w = 0; w < 16; w++) s += accw[d][w];
        smag[d] = sqrtf(s);
    }
    __syncthreads();
    float lam = softplus_lambda(kpar[l]);
    float S = g_partB[((size_t)b * NCH + ch) * DD + d];
    #pragma unroll 4
    for (int i = 0; i < CS; i++) {
        size_t idx = base + (size_t)i * DD;
        S = g_h[idx] + lam * S;
        g_s1[idx] = fabsf(smag[i] * S);
    }
}

// ---------------- block reduction ----------------
__device__ __forceinline__ float block_reduce(float v, float* sh) {
    int lane = threadIdx.x & 31, wid = threadIdx.x >> 5;
    #pragma unroll
    for (int o = 16; o; o >>= 1) v += __shfl_down_sync(0xffffffffu, v, o);
    if (lane == 0) sh[wid] = v;
    __syncthreads();
    float r = 0.f;
    if (threadIdx.x < (blockDim.x >> 5)) r = sh[threadIdx.x];
    if (wid == 0) {
        #pragma unroll
        for (int o = 16; o; o >>= 1) r += __shfl_down_sync(0xffffffffu, r, o);
        if (lane == 0) sh[0] = r;
    }
    __syncthreads();
    r = sh[0];
    __syncthreads();
    return r;
}

// ---------------- layernorm -> pre-split bf16 s2 ----------------
__global__ void layernorm_kernel(const float* __restrict__ gamma, const float* __restrict__ beta) {
    __shared__ float row[DD];
    __shared__ float sh[32];
    int tok = blockIdx.x;
    size_t base = (size_t)tok * DD;
    float s = 0.f;
    for (int d = threadIdx.x; d < DD; d += blockDim.x) {
        float v = g_s1[base + d];
        row[d] = v;
        s += v;
    }
    s = block_reduce(s, sh);
    float mu = s * (1.0f / DD);
    float q = 0.f;
    for (int d = threadIdx.x; d < DD; d += blockDim.x) {
        float v = row[d] - mu;
        q += v * v;
    }
    q = block_reduce(q, sh);
    float rstd = rsqrtf(q * (1.0f / DD) + 1e-3f);
    for (int d = threadIdx.x; d < DD; d += blockDim.x) {
        float y = (row[d] - mu) * rstd * gamma[d] + beta[d];
        __nv_bfloat16 h = __float2bfloat16(y);
        g_s2h[base + d] = h;
        g_s2l[base + d] = __float2bfloat16(y - __bfloat162float(h));
    }
}

// ================= bf16x3 tensor-core GEMM (ldmatrix + m16n8k16) ===========
// R4 structure EXACTLY; only the staging mechanism changed to cp.async
// (__pipeline_memcpy_async) with the identical smem layout/addresses.
#define AROWB 48
#define A_TILE_B (128*AROWB)           // 6144
#define BROWB 528
#define B_TILE_B (16*BROWB)            // 8448
#define SM_A_BYTES (4*A_TILE_B)
#define SM_B_BYTES (4*B_TILE_B)
#define GSMEM (SM_A_BYTES + SM_B_BYTES)  // 58368

#define LDSM4(r0,r1,r2,r3,addr) \
    asm volatile("ldmatrix.sync.aligned.m8n8.x4.shared.b16 {%0,%1,%2,%3},[%4];" \
                 : "=r"(r0),"=r"(r1),"=r"(r2),"=r"(r3) : "r"(addr))
#define LDSM4T(r0,r1,r2,r3,addr) \
    asm volatile("ldmatrix.sync.aligned.m8n8.x4.trans.shared.b16 {%0,%1,%2,%3},[%4];" \
                 : "=r"(r0),"=r"(r1),"=r"(r2),"=r"(r3) : "r"(addr))
#define MMA_BF16(c,a,b0,b1) \
    asm volatile("mma.sync.aligned.m16n8k16.row.col.f32.bf16.bf16.f32 " \
                 "{%0,%1,%2,%3},{%4,%5,%6,%7},{%8,%9},{%0,%1,%2,%3};" \
                 : "+f"(c[0]),"+f"(c[1]),"+f"(c[2]),"+f"(c[3]) \
                 : "r"(a[0]),"r"(a[1]),"r"(a[2]),"r"(a[3]),"r"(b0),"r"(b1))

__device__ __forceinline__ float gelu_exact(float c) {
    return 0.5f * c * (1.0f + erff(c * 0.70710678118654752f));
}

// cp.async staging of one K16 stage into buffer p (same addresses as R4 sts_tile)
__device__ __forceinline__ void fill_cp(char* sbase, int p,
                                        const __nv_bfloat16* __restrict__ Ah,
                                        const __nv_bfloat16* __restrict__ Al,
                                        const __nv_bfloat16* __restrict__ Bh,
                                        const __nv_bfloat16* __restrict__ Bl,
                                        int bm, int bn, int k0, int K, int N, int tid) {
    int arow = tid >> 1, aseg = tid & 1;
    char* A = sbase + p * (2 * A_TILE_B);
    size_t abase = (size_t)(bm + arow) * K + k0 + aseg * 8;
    __pipeline_memcpy_async(A + arow * AROWB + aseg * 16, Ah + abase, 16);
    __pipeline_memcpy_async(A + A_TILE_B + arow * AROWB + aseg * 16, Al + abase, 16);
    int k = tid >> 5, ng = tid & 31;
    char* Bp = sbase + SM_A_BYTES + p * (2 * B_TILE_B);
    size_t b0 = (size_t)(k0 + k) * N + bn + ng * 8;
    size_t b1 = (size_t)(k0 + k + 8) * N + bn + ng * 8;
    __pipeline_memcpy_async(Bp + k * BROWB + ng * 16, Bh + b0, 16);
    __pipeline_memcpy_async(Bp + (k + 8) * BROWB + ng * 16, Bh + b1, 16);
    __pipeline_memcpy_async(Bp + B_TILE_B + k * BROWB + ng * 16, Bl + b0, 16);
    __pipeline_memcpy_async(Bp + B_TILE_B + (k + 8) * BROWB + ng * 16, Bl + b1, 16);
}

template <int EPI>
__device__ __forceinline__ void gemm_bf16x3(const __nv_bfloat16* __restrict__ Ah,
                                            const __nv_bfloat16* __restrict__ Al,
                                            const __nv_bfloat16* __restrict__ Bh,
                                            const __nv_bfloat16* __restrict__ Bl,
                                            const float* __restrict__ bias,
                                            float* __restrict__ Cf,
                                            __nv_bfloat16* __restrict__ Ch,
                                            __nv_bfloat16* __restrict__ Cl,
                                            int M, int N, int K) {
    extern __shared__ char smc[];
    const int bm = blockIdx.y * 128;
    const int bn = blockIdx.x * 256;
    const int tid = threadIdx.x;
    const int lane = tid & 31;
    const int wid = tid >> 5;
    const int wm = wid >> 2, wn = wid & 3;
    const int g = lane >> 2, kq = lane & 3;
    const int lrow = lane & 7, lmat = lane >> 3;

    const uint32_t smem_u32 = (uint32_t)__cvta_generic_to_shared(smc);
    const uint32_t aoff = smem_u32 + (uint32_t)((wm * 64 + (lmat & 1) * 8 + lrow) * AROWB + (lmat >> 1) * 16);
    const uint32_t boff = smem_u32 + SM_A_BYTES +
                          (uint32_t)(((lmat & 1) * 8 + lrow) * BROWB + (wn * 64 + (lmat >> 1) * 8) * 2);

    float acc[4][8][4];
    #pragma unroll
    for (int mt = 0; mt < 4; mt++)
        #pragma unroll
        for (int nt = 0; nt < 8; nt++)
            #pragma unroll
            for (int r = 0; r < 4; r++) acc[mt][nt][r] = 0.f;

    const int KT = K >> 4;

    fill_cp(smc, 0, Ah, Al, Bh, Bl, bm, bn, 0, K, N, tid);
    __pipeline_commit();

    for (int kt = 0; kt < KT; kt++) {
        const int p = kt & 1;
        const bool more = (kt + 1 < KT);
        if (more) {
            fill_cp(smc, p ^ 1, Ah, Al, Bh, Bl, bm, bn, (kt + 1) << 4, K, N, tid);
            __pipeline_commit();
            __pipeline_wait_prior(1);
        } else {
            __pipeline_wait_prior(0);
        }
        __syncthreads();

        const uint32_t aB = aoff + p * (2 * A_TILE_B);
        const uint32_t bB = boff + p * (2 * B_TILE_B);
        uint32_t aH[4][4], aL[4][4];
        #pragma unroll
        for (int mt = 0; mt < 4; mt++) {
            LDSM4(aH[mt][0], aH[mt][1], aH[mt][2], aH[mt][3], aB + mt * (16 * AROWB));
            LDSM4(aL[mt][0], aL[mt][1], aL[mt][2], aL[mt][3], aB + mt * (16 * AROWB) + A_TILE_B);
        }
        #pragma unroll
        for (int ntp = 0; ntp < 4; ntp++) {
            uint32_t bh[4], bl[4];
            LDSM4T(bh[0], bh[1], bh[2], bh[3], bB + ntp * 32);
            LDSM4T(bl[0], bl[1], bl[2], bl[3], bB + ntp * 32 + B_TILE_B);
            #pragma unroll
            for (int w = 0; w < 2; w++) {
                const int nt = 2 * ntp + w;
                #pragma unroll
                for (int mt = 0; mt < 4; mt++) {
                    MMA_BF16(acc[mt][nt], aL[mt], bh[2 * w], bh[2 * w + 1]);
                    MMA_BF16(acc[mt][nt], aH[mt], bl[2 * w], bl[2 * w + 1]);
                    MMA_BF16(acc[mt][nt], aH[mt], bh[2 * w], bh[2 * w + 1]);
                }
            }
        }
        __syncthreads();
    }

    // epilogue
    #pragma unroll
    for (int mt = 0; mt < 4; mt++) {
        const int m0 = bm + wm * 64 + mt * 16 + g;
        #pragma unroll
        for (int nt = 0; nt < 8; nt++) {
            const int n0 = bn + wn * 64 + nt * 8 + kq * 2;
            const float b0 = bias[n0], b1 = bias[n0 + 1];
            if (EPI == 0) {
                float v0 = gelu_exact(acc[mt][nt][0] + b0);
                float v1 = gelu_exact(acc[mt][nt][1] + b1);
                float v2 = gelu_exact(acc[mt][nt][2] + b0);
                float v3 = gelu_exact(acc[mt][nt][3] + b1);
                __nv_bfloat16 h0 = __float2bfloat16(v0), h1 = __float2bfloat16(v1);
                __nv_bfloat16 h2 = __float2bfloat16(v2), h3 = __float2bfloat16(v3);
                uint32_t hw0 = (uint32_t)__bfloat16_as_ushort(h0) | ((uint32_t)__bfloat16_as_ushort(h1) << 16);
                uint32_t hw1 = (uint32_t)__bfloat16_as_ushort(h2) | ((uint32_t)__bfloat16_as_ushort(h3) << 16);
                __nv_bfloat16 l0 = __float2bfloat16(v0 - __bfloat162float(h0));
                __nv_bfloat16 l1 = __float2bfloat16(v1 - __bfloat162float(h1));
                __nv_bfloat16 l2 = __float2bfloat16(v2 - __bfloat162float(h2));
                __nv_bfloat16 l3 = __float2bfloat16(v3 - __bfloat162float(h3));
                uint32_t lw0 = (uint32_t)__bfloat16_as_ushort(l0) | ((uint32_t)__bfloat16_as_ushort(l1) << 16);
                uint32_t lw1 = (uint32_t)__bfloat16_as_ushort(l2) | ((uint32_t)__bfloat16_as_ushort(l3) << 16);
                size_t i0 = ((size_t)m0 * N + n0) >> 1;
                size_t i1 = ((size_t)(m0 + 8) * N + n0) >> 1;
                ((uint32_t*)Ch)[i0] = hw0;
                ((uint32_t*)Cl)[i0] = lw0;
                ((uint32_t*)Ch)[i1] = hw1;
                ((uint32_t*)Cl)[i1] = lw1;
            } else {
                float2* p0 = (float2*)&Cf[(size_t)m0 * N + n0];
                float2* p1 = (float2*)&Cf[(size_t)(m0 + 8) * N + n0];
                float2 o0 = *p0, o1 = *p1;
                o0.x += acc[mt][nt][0] + b0;
                o0.y += acc[mt][nt][1] + b1;
                o1.x += acc[mt][nt][2] + b0;
                o1.y += acc[mt][nt][3] + b1;
                *p0 = o0;
                *p1 = o1;
            }
        }
    }
}

__global__ void __launch_bounds__(256, 1) gemm1_bf16(const float* __restrict__ b1, int l) {
    gemm_bf16x3<0>(g_s2h, g_s2l, g_w1h + (size_t)l * DD * HH, g_w1l + (size_t)l * DD * HH,
                   b1, nullptr, g_acth, g_actl, NTOK, HH, DD);
}
__global__ void __launch_bounds__(256, 1) gemm2_bf16(const float* __restrict__ b2, int l) {
    gemm_bf16x3<1>(g_acth, g_actl, g_w2h + (size_t)l * DD * HH, g_w2l + (size_t)l * DD * HH,
                   b2, g_h, nullptr, nullptr, NTOK, DD, HH);
}

// ---------------- fp32 SGEMM for output projection --------------------------
__global__ void __launch_bounds__(256) gemm_out_kernel(const float* __restrict__ embed,
                                                       float* __restrict__ out) {
    __shared__ float As[16][128];
    __shared__ float Bs[16][132];
    const float* A = g_h;
    const float* B = embed;
    const int N = VV, K = DD;
    const int bm = blockIdx.y * 128, bn = blockIdx.x * 128;
    const int tid = threadIdx.x;
    const int ty = tid >> 4, tx = tid & 15;
    float acc[8][8];
    #pragma unroll
    for (int i = 0; i < 8; i++)
        #pragma unroll
        for (int j = 0; j < 8; j++) acc[i][j] = 0.f;

    for (int k0 = 0; k0 < K; k0 += 16) {
        #pragma unroll
        for (int r = 0; r < 2; r++) {
            int slot = tid + r * 256;
            int arow = slot >> 2;
            int ac = (slot & 3) << 2;
            const float4 v = *(const float4*)(A + (size_t)(bm + arow) * K + k0 + ac);
            As[ac + 0][arow] = v.x;
            As[ac + 1][arow] = v.y;
            As[ac + 2][arow] = v.z;
            As[ac + 3][arow] = v.w;
        }
        #pragma unroll
        for (int r = 0; r < 2; r++) {
            int slot = tid + r * 256;
            int nr = slot >> 2;
            int kc = (slot & 3) << 2;
            const float4 v = *(const float4*)(B + (size_t)(bn + nr) * K + k0 + kc);
            Bs[kc + 0][nr] = v.x;
            Bs[kc + 1][nr] = v.y;
            Bs[kc + 2][nr] = v.z;
            Bs[kc + 3][nr] = v.w;
        }
        __syncthreads();
        #pragma unroll
        for (int kk = 0; kk < 16; kk++) {
            float ra[8], rb[8];
            *(float4*)&ra[0] = *(const float4*)&As[kk][ty * 8];
            *(float4*)&ra[4] = *(const float4*)&As[kk][ty * 8 + 4];
            *(float4*)&rb[0] = *(const float4*)&Bs[kk][tx * 8];
            *(float4*)&rb[4] = *(const float4*)&Bs[kk][tx * 8 + 4];
            #pragma unroll
            for (int i = 0; i < 8; i++)
                #pragma unroll
                for (int j = 0; j < 8; j++) acc[i][j] += ra[i] * rb[j];
        }
        __syncthreads();
    }

    int row0 = bm + ty * 8, col0 = bn + tx * 8;
    #pragma unroll
    for (int i = 0; i < 8; i++)
        #pragma unroll
        for (int j = 0; j < 8; j++)
            out[(size_t)(row0 + i) * N + col0 + j] = acc[i][j];
}

// ---------------- launcher ----------------
extern "C" void kernel_launch(void* const* d_in, const int* in_sizes, int n_in,
                              void* d_out, int out_size) {
    const int*   x     = (const int*)d_in[0];
    const float* embed = (const float*)d_in[1];
    const float* kpar  = (const float*)d_in[2];
    const float* gamma = (const float*)d_in[3];
    const float* beta  = (const float*)d_in[4];
    const float* W1    = (const float*)d_in[5];
    const float* b1    = (const float*)d_in[6];
    const float* W2    = (const float*)d_in[7];
    const float* b2    = (const float*)d_in[8];
    float* out = (float*)d_out;

    cudaFuncSetAttribute(gemm1_bf16, cudaFuncAttributeMaxDynamicSharedMemorySize, GSMEM);
    cudaFuncSetAttribute(gemm2_bf16, cudaFuncAttributeMaxDynamicSharedMemorySize, GSMEM);

    dim3 sg(BB, NCH);

    embed_cumprod_kernel<<<NTOK / 8, 256>>>(x, embed);
    split_weights_kernel<<<(3 * DD * HH) / 256, 256>>>(W1, W2);
    boundA_kernel<<<sg, DD>>>();
    boundB_kernel<<<BB, DD>>>();
    boundC_kernel<<<sg, DD>>>();

    for (int l = 0; l < 3; l++) {
        scanA_kernel<<<sg, DD>>>(kpar, l);
        scanB_kernel<<<BB, DD>>>(kpar, l);
        magdecayC_kernel<<<sg, DD>>>(kpar, l);
        layernorm_kernel<<<NTOK, 128>>>(gamma + l * DD, beta + l * DD);
        gemm1_bf16<<<dim3(HH / 256, NTOK / 128), 256, GSMEM>>>(b1 + l * HH, l);
        gemm2_bf16<<<dim3(DD / 256, NTOK / 128), 256, GSMEM>>>(b2 + l * DD, l);
    }
    gemm_out_kernel<<<dim3(VV / 128, NTOK / 128), 256>>>(embed, out);
}

// round 9
// speedup vs baseline: 1.0910x; 1.0910x over previous
#include <cuda_runtime.h>
#include <cuda_bf16.h>
#include <math.h>
#include <stdint.h>

#define BB 4
#define TT 2048
#define DD 512
#define HH 2048
#define VV 256
#define NTOK (BB*TT)   // 8192
#define CS 64
#define NCH (TT/CS)

// ---------------- scratch ----------------
__device__ __align__(128) float g_h[NTOK*DD];
__device__ __align__(128) float g_s1[NTOK*DD];
__device__ __align__(128) float g_partA[BB*NCH*DD];
__device__ __align__(128) float g_partB[BB*NCH*DD];
__device__ __align__(128) __nv_bfloat16 g_s2h[NTOK*DD];
__device__ __align__(128) __nv_bfloat16 g_s2l[NTOK*DD];
__device__ __align__(128) __nv_bfloat16 g_acth[(size_t)NTOK*HH];
__device__ __align__(128) __nv_bfloat16 g_actl[(size_t)NTOK*HH];
__device__ __align__(128) __nv_bfloat16 g_w1h[3*DD*HH];
__device__ __align__(128) __nv_bfloat16 g_w1l[3*DD*HH];
__device__ __align__(128) __nv_bfloat16 g_w2h[3*DD*HH];
__device__ __align__(128) __nv_bfloat16 g_w2l[3*DD*HH];

__device__ __forceinline__ float softplus_lambda(float kv) {
    float sp = (kv > 0.f) ? (kv + log1pf(expf(-kv))) : log1pf(expf(kv));
    return expf(-sp);
}

// ---------------- weight split prepass (bf16 hi/lo) ----------------
__global__ void split_weights_kernel(const float* __restrict__ W1, const float* __restrict__ W2) {
    size_t i = (size_t)blockIdx.x * blockDim.x + threadIdx.x;
    float v1 = W1[i];
    __nv_bfloat16 h1 = __float2bfloat16(v1);
    g_w1h[i] = h1;
    g_w1l[i] = __float2bfloat16(v1 - __bfloat162float(h1));
    float v2 = W2[i];
    __nv_bfloat16 h2 = __float2bfloat16(v2);
    g_w2h[i] = h2;
    g_w2l[i] = __float2bfloat16(v2 - __bfloat162float(h2));
}

// ---------------- fused embed gather + tanh(cumprod) (warp per token) ------
__global__ void embed_cumprod_kernel(const int* __restrict__ x, const float* __restrict__ embed) {
    int w = threadIdx.x >> 5;
    int lane = threadIdx.x & 31;
    int tok = blockIdx.x * 8 + w;
    const float* src = embed + (size_t)x[tok] * DD;
    size_t base = (size_t)tok * DD + lane * 16;
    float v[16];
    #pragma unroll
    for (int j = 0; j < 4; j++)
        *(float4*)&v[j * 4] = *(const float4*)(src + lane * 16 + j * 4);
    float c[16];
    float run = 1.f;
    #pragma unroll
    for (int j = 0; j < 16; j++) {
        run *= v[j];
        c[j] = run;
    }
    float incl = run;
    #pragma unroll
    for (int off = 1; off < 32; off <<= 1) {
        float p = __shfl_up_sync(0xffffffffu, incl, off);
        if (lane >= off) incl *= p;
    }
    float pre = __shfl_up_sync(0xffffffffu, incl, 1);
    if (lane == 0) pre = 1.f;
    #pragma unroll
    for (int j = 0; j < 4; j++) {
        *(float4*)&g_h[base + j * 4] = *(const float4*)&v[j * 4];
        float4 o;
        o.x = tanhf(pre * c[j * 4 + 0]);
        o.y = tanhf(pre * c[j * 4 + 1]);
        o.z = tanhf(pre * c[j * 4 + 2]);
        o.w = tanhf(pre * c[j * 4 + 3]);
        *(float4*)&g_s1[base + j * 4] = o;
    }
}

// ============= boundary scan ================================================
__global__ void boundA_kernel() {
    int b = blockIdx.x, ch = blockIdx.y, d = threadIdx.x;
    size_t base = ((size_t)b * TT + ch * CS) * DD + d;
    float s = 0.f;
    #pragma unroll 8
    for (int i = 0; i < CS; i++) s += g_s1[base + (size_t)i * DD];
    g_partA[((size_t)b * NCH + ch) * DD + d] = s;
}

__global__ void boundB_kernel() {
    int b = blockIdx.x, d = threadIdx.x;
    float c = 0.f;
    for (int ch = 0; ch < NCH; ch++) {
        size_t idx = ((size_t)b * NCH + ch) * DD + d;
        float v = g_partA[idx];
        g_partA[idx] = c;
        c += v;
    }
}

__global__ void boundC_kernel() {
    int b = blockIdx.x, ch = blockIdx.y, d = threadIdx.x;
    size_t base = ((size_t)b * TT + ch * CS) * DD + d;
    float acc = g_partA[((size_t)b * NCH + ch) * DD + d];
    #pragma unroll 4
    for (int i = 0; i < CS; i++) {
        size_t idx = base + (size_t)i * DD;
        acc += g_s1[idx];
        g_h[idx] = g_h[idx] * (1.0f + acc);
    }
}

// ============= per-layer scans =============================================
__global__ void scanA_kernel(const float* __restrict__ kpar, int l) {
    int b = blockIdx.x, ch = blockIdx.y, d = threadIdx.x;
    float lam = softplus_lambda(kpar[l]);
    size_t base = ((size_t)b * TT + ch * CS) * DD + d;
    float s = 0.f, loc = 0.f;
    #pragma unroll 4
    for (int i = 0; i < CS; i++) {
        float v = g_h[base + (size_t)i * DD];
        s += v;
        loc = v + lam * loc;
    }
    size_t pidx = ((size_t)b * NCH + ch) * DD + d;
    g_partA[pidx] = s;
    g_partB[pidx] = loc;
}

__global__ void scanB_kernel(const float* __restrict__ kpar, int l) {
    int b = blockIdx.x, d = threadIdx.x;
    float lam = softplus_lambda(kpar[l]);
    float lamCS = powf(lam, (float)CS);
    float c1 = 0.f, c2 = 0.f;
    for (int ch = 0; ch < NCH; ch++) {
        size_t idx = ((size_t)b * NCH + ch) * DD + d;
        float a = g_partA[idx];
        float v = g_partB[idx];
        g_partA[idx] = c1;
        g_partB[idx] = c2;
        c1 += a;
        c2 = v + lamCS * c2;
    }
}

// ======== fused mag + decay-ctx ============================================
__global__ void magdecayC_kernel(const float* __restrict__ kpar, int l) {
    __shared__ float accw[CS][17];
    __shared__ float smag[CS];
    int b = blockIdx.x, ch = blockIdx.y;
    int d = threadIdx.x;
    int lane = d & 31, wid = d >> 5;
    int t0 = ch * CS;
    size_t base = ((size_t)b * TT + t0) * DD + d;
    float acc = g_partA[((size_t)b * NCH + ch) * DD + d];
    float hp = (t0 > 0) ? g_h[base - DD] : 0.f;
    #pragma unroll 4
    for (int i = 0; i < CS; i++) {
        float v = g_h[base + (size_t)i * DD];
        acc += v;
        float diff = acc - hp;
        float sq = diff * diff;
        #pragma unroll
        for (int o = 16; o; o >>= 1) sq += __shfl_down_sync(0xffffffffu, sq, o);
        if (lane == 0) accw[i][wid] = sq;
        hp = v;
    }
    __syncthreads();
    if (d < CS) {
        float s = 0.f;
        #pragma unroll
        for (int w = 0; w < 16; w++) s += accw[d][w];
        smag[d] = sqrtf(s);
    }
    __syncthreads();
    float lam = softplus_lambda(kpar[l]);
    float S = g_partB[((size_t)b * NCH + ch) * DD + d];
    #pragma unroll 4
    for (int i = 0; i < CS; i++) {
        size_t idx = base + (size_t)i * DD;
        S = g_h[idx] + lam * S;
        g_s1[idx] = fabsf(smag[i] * S);
    }
}

// ---------------- block reduction ----------------
__device__ __forceinline__ float block_reduce(float v, float* sh) {
    int lane = threadIdx.x & 31, wid = threadIdx.x >> 5;
    #pragma unroll
    for (int o = 16; o; o >>= 1) v += __shfl_down_sync(0xffffffffu, v, o);
    if (lane == 0) sh[wid] = v;
    __syncthreads();
    float r = 0.f;
    if (threadIdx.x < (blockDim.x >> 5)) r = sh[threadIdx.x];
    if (wid == 0) {
        #pragma unroll
        for (int o = 16; o; o >>= 1) r += __shfl_down_sync(0xffffffffu, r, o);
        if (lane == 0) sh[0] = r;
    }
    __syncthreads();
    r = sh[0];
    __syncthreads();
    return r;
}

// ---------------- layernorm -> pre-split bf16 s2 ----------------
__global__ void layernorm_kernel(const float* __restrict__ gamma, const float* __restrict__ beta) {
    __shared__ float row[DD];
    __shared__ float sh[32];
    int tok = blockIdx.x;
    size_t base = (size_t)tok * DD;
    float s = 0.f;
    for (int d = threadIdx.x; d < DD; d += blockDim.x) {
        float v = g_s1[base + d];
        row[d] = v;
        s += v;
    }
    s = block_reduce(s, sh);
    float mu = s * (1.0f / DD);
    float q = 0.f;
    for (int d = threadIdx.x; d < DD; d += blockDim.x) {
        float v = row[d] - mu;
        q += v * v;
    }
    q = block_reduce(q, sh);
    float rstd = rsqrtf(q * (1.0f / DD) + 1e-3f);
    for (int d = threadIdx.x; d < DD; d += blockDim.x) {
        float y = (row[d] - mu) * rstd * gamma[d] + beta[d];
        __nv_bfloat16 h = __float2bfloat16(y);
        g_s2h[base + d] = h;
        g_s2l[base + d] = __float2bfloat16(y - __bfloat162float(h));
    }
}

// ================= bf16x3 tensor-core GEMM (ldmatrix + m16n8k16) ===========
// 128x128 block tile, 8 warps (2m x 4n, warp tile 64x32), register staging,
// double-buffered K16 stages, 2 CTAs/SM.
#define AROWB 48
#define A_TILE_B (128*AROWB)           // 6144
#define BROWB 272                      // 128 cols * 2B + 16 pad
#define B_TILE_B (16*BROWB)            // 4352
#define SM_A_BYTES (4*A_TILE_B)        // 24576 (2 buf x hi/lo)
#define SM_B_BYTES (4*B_TILE_B)        // 17408
#define GSMEM (SM_A_BYTES + SM_B_BYTES)  // 41984

#define LDSM4(r0,r1,r2,r3,addr) \
    asm volatile("ldmatrix.sync.aligned.m8n8.x4.shared.b16 {%0,%1,%2,%3},[%4];" \
                 : "=r"(r0),"=r"(r1),"=r"(r2),"=r"(r3) : "r"(addr))
#define LDSM4T(r0,r1,r2,r3,addr) \
    asm volatile("ldmatrix.sync.aligned.m8n8.x4.trans.shared.b16 {%0,%1,%2,%3},[%4];" \
                 : "=r"(r0),"=r"(r1),"=r"(r2),"=r"(r3) : "r"(addr))
#define MMA_BF16(c,a,b0,b1) \
    asm volatile("mma.sync.aligned.m16n8k16.row.col.f32.bf16.bf16.f32 " \
                 "{%0,%1,%2,%3},{%4,%5,%6,%7},{%8,%9},{%0,%1,%2,%3};" \
                 : "+f"(c[0]),"+f"(c[1]),"+f"(c[2]),"+f"(c[3]) \
                 : "r"(a[0]),"r"(a[1]),"r"(a[2]),"r"(a[3]),"r"(b0),"r"(b1))

struct StageRegs { uint4 ah, al, bh, bl; };

__device__ __forceinline__ void ldg_tile(const __nv_bfloat16* __restrict__ Ah,
                                         const __nv_bfloat16* __restrict__ Al,
                                         const __nv_bfloat16* __restrict__ Bh,
                                         const __nv_bfloat16* __restrict__ Bl,
                                         int bm, int bn, int k0, int K, int N,
                                         int tid, StageRegs& r) {
    int arow = tid >> 1, aseg = tid & 1;
    size_t abase = (size_t)(bm + arow) * K + k0 + aseg * 8;
    r.ah = *(const uint4*)(Ah + abase);
    r.al = *(const uint4*)(Al + abase);
    int k = tid >> 4, ng = tid & 15;           // 16 k-rows x 16 col-groups
    size_t bbase = (size_t)(k0 + k) * N + bn + ng * 8;
    r.bh = *(const uint4*)(Bh + bbase);
    r.bl = *(const uint4*)(Bl + bbase);
}

__device__ __forceinline__ void sts_tile(char* sbase, int p, int tid, const StageRegs& r) {
    int arow = tid >> 1, aseg = tid & 1;
    char* A = sbase + p * (2 * A_TILE_B);
    *(uint4*)(A + arow * AROWB + aseg * 16) = r.ah;
    *(uint4*)(A + A_TILE_B + arow * AROWB + aseg * 16) = r.al;
    int k = tid >> 4, ng = tid & 15;
    char* Bp = sbase + SM_A_BYTES + p * (2 * B_TILE_B);
    *(uint4*)(Bp + k * BROWB + ng * 16) = r.bh;
    *(uint4*)(Bp + B_TILE_B + k * BROWB + ng * 16) = r.bl;
}

__device__ __forceinline__ float gelu_exact(float c) {
    return 0.5f * c * (1.0f + erff(c * 0.70710678118654752f));
}

// EPI 0: bias+GELU -> split bf16 Ch/Cl.  EPI 1: bias + accumulate into Cf.
template <int EPI>
__device__ __forceinline__ void gemm_bf16x3(const __nv_bfloat16* __restrict__ Ah,
                                            const __nv_bfloat16* __restrict__ Al,
                                            const __nv_bfloat16* __restrict__ Bh,
                                            const __nv_bfloat16* __restrict__ Bl,
                                            const float* __restrict__ bias,
                                            float* __restrict__ Cf,
                                            __nv_bfloat16* __restrict__ Ch,
                                            __nv_bfloat16* __restrict__ Cl,
                                            int M, int N, int K) {
    extern __shared__ char smc[];
    const int bm = blockIdx.y * 128;
    const int bn = blockIdx.x * 128;
    const int tid = threadIdx.x;
    const int lane = tid & 31;
    const int wid = tid >> 5;
    const int wm = wid >> 2, wn = wid & 3;     // warp tile 64m x 32n
    const int g = lane >> 2, kq = lane & 3;
    const int lrow = lane & 7, lmat = lane >> 3;

    const uint32_t smem_u32 = (uint32_t)__cvta_generic_to_shared(smc);
    const uint32_t aoff = smem_u32 + (uint32_t)((wm * 64 + (lmat & 1) * 8 + lrow) * AROWB + (lmat >> 1) * 16);
    const uint32_t boff = smem_u32 + SM_A_BYTES +
                          (uint32_t)(((lmat & 1) * 8 + lrow) * BROWB + (wn * 32 + (lmat >> 1) * 8) * 2);

    float acc[4][4][4];
    #pragma unroll
    for (int mt = 0; mt < 4; mt++)
        #pragma unroll
        for (int nt = 0; nt < 4; nt++)
            #pragma unroll
            for (int r = 0; r < 4; r++) acc[mt][nt][r] = 0.f;

    const int KT = K >> 4;
    StageRegs sr;
    ldg_tile(Ah, Al, Bh, Bl, bm, bn, 0, K, N, tid, sr);
    sts_tile(smc, 0, tid, sr);
    __syncthreads();

    for (int kt = 0; kt < KT; kt++) {
        const int p = kt & 1;
        const bool more = (kt + 1 < KT);
        if (more) ldg_tile(Ah, Al, Bh, Bl, bm, bn, (kt + 1) << 4, K, N, tid, sr);

        const uint32_t aB = aoff + p * (2 * A_TILE_B);
        const uint32_t bB = boff + p * (2 * B_TILE_B);
        uint32_t aH[4][4], aL[4][4];
        #pragma unroll
        for (int mt = 0; mt < 4; mt++) {
            LDSM4(aH[mt][0], aH[mt][1], aH[mt][2], aH[mt][3], aB + mt * (16 * AROWB));
            LDSM4(aL[mt][0], aL[mt][1], aL[mt][2], aL[mt][3], aB + mt * (16 * AROWB) + A_TILE_B);
        }
        #pragma unroll
        for (int ntp = 0; ntp < 2; ntp++) {
            uint32_t bh[4], bl[4];
            LDSM4T(bh[0], bh[1], bh[2], bh[3], bB + ntp * 32);
            LDSM4T(bl[0], bl[1], bl[2], bl[3], bB + ntp * 32 + B_TILE_B);
            #pragma unroll
            for (int w = 0; w < 2; w++) {
                const int nt = 2 * ntp + w;
                #pragma unroll
                for (int mt = 0; mt < 4; mt++) {
                    MMA_BF16(acc[mt][nt], aL[mt], bh[2 * w], bh[2 * w + 1]);
                    MMA_BF16(acc[mt][nt], aH[mt], bl[2 * w], bl[2 * w + 1]);
                    MMA_BF16(acc[mt][nt], aH[mt], bh[2 * w], bh[2 * w + 1]);
                }
            }
        }
        if (more) sts_tile(smc, p ^ 1, tid, sr);
        __syncthreads();
    }

    // epilogue
    #pragma unroll
    for (int mt = 0; mt < 4; mt++) {
        const int m0 = bm + wm * 64 + mt * 16 + g;
        #pragma unroll
        for (int nt = 0; nt < 4; nt++) {
            const int n0 = bn + wn * 32 + nt * 8 + kq * 2;
            const float b0 = bias[n0], b1 = bias[n0 + 1];
            if (EPI == 0) {
                float v0 = gelu_exact(acc[mt][nt][0] + b0);
                float v1 = gelu_exact(acc[mt][nt][1] + b1);
                float v2 = gelu_exact(acc[mt][nt][2] + b0);
                float v3 = gelu_exact(acc[mt][nt][3] + b1);
                __nv_bfloat16 h0 = __float2bfloat16(v0), h1 = __float2bfloat16(v1);
                __nv_bfloat16 h2 = __float2bfloat16(v2), h3 = __float2bfloat16(v3);
                uint32_t hw0 = (uint32_t)__bfloat16_as_ushort(h0) | ((uint32_t)__bfloat16_as_ushort(h1) << 16);
                uint32_t hw1 = (uint32_t)__bfloat16_as_ushort(h2) | ((uint32_t)__bfloat16_as_ushort(h3) << 16);
                __nv_bfloat16 l0 = __float2bfloat16(v0 - __bfloat162float(h0));
                __nv_bfloat16 l1 = __float2bfloat16(v1 - __bfloat162float(h1));
                __nv_bfloat16 l2 = __float2bfloat16(v2 - __bfloat162float(h2));
                __nv_bfloat16 l3 = __float2bfloat16(v3 - __bfloat162float(h3));
                uint32_t lw0 = (uint32_t)__bfloat16_as_ushort(l0) | ((uint32_t)__bfloat16_as_ushort(l1) << 16);
                uint32_t lw1 = (uint32_t)__bfloat16_as_ushort(l2) | ((uint32_t)__bfloat16_as_ushort(l3) << 16);
                size_t i0 = ((size_t)m0 * N + n0) >> 1;
                size_t i1 = ((size_t)(m0 + 8) * N + n0) >> 1;
                ((uint32_t*)Ch)[i0] = hw0;
                ((uint32_t*)Cl)[i0] = lw0;
                ((uint32_t*)Ch)[i1] = hw1;
                ((uint32_t*)Cl)[i1] = lw1;
            } else {
                float2* p0 = (float2*)&Cf[(size_t)m0 * N + n0];
                float2* p1 = (float2*)&Cf[(size_t)(m0 + 8) * N + n0];
                float2 o0 = *p0, o1 = *p1;
                o0.x += acc[mt][nt][0] + b0;
                o0.y += acc[mt][nt][1] + b1;
                o1.x += acc[mt][nt][2] + b0;
                o1.y += acc[mt][nt][3] + b1;
                *p0 = o0;
                *p1 = o1;
            }
        }
    }
}

__global__ void __launch_bounds__(256, 2) gemm1_bf16(const float* __restrict__ b1, int l) {
    gemm_bf16x3<0>(g_s2h, g_s2l, g_w1h + (size_t)l * DD * HH, g_w1l + (size_t)l * DD * HH,
                   b1, nullptr, g_acth, g_actl, NTOK, HH, DD);
}
__global__ void __launch_bounds__(256, 2) gemm2_bf16(const float* __restrict__ b2, int l) {
    gemm_bf16x3<1>(g_acth, g_actl, g_w2h + (size_t)l * DD * HH, g_w2l + (size_t)l * DD * HH,
                   b2, g_h, nullptr, nullptr, NTOK, DD, HH);
}

// ---------------- fp32 SGEMM for output projection --------------------------
__global__ void __launch_bounds__(256) gemm_out_kernel(const float* __restrict__ embed,
                                                       float* __restrict__ out) {
    __shared__ float As[16][128];
    __shared__ float Bs[16][132];
    const float* A = g_h;
    const float* B = embed;
    const int N = VV, K = DD;
    const int bm = blockIdx.y * 128, bn = blockIdx.x * 128;
    const int tid = threadIdx.x;
    const int ty = tid >> 4, tx = tid & 15;
    float acc[8][8];
    #pragma unroll
    for (int i = 0; i < 8; i++)
        #pragma unroll
        for (int j = 0; j < 8; j++) acc[i][j] = 0.f;

    for (int k0 = 0; k0 < K; k0 += 16) {
        #pragma unroll
        for (int r = 0; r < 2; r++) {
            int slot = tid + r * 256;
            int arow = slot >> 2;
            int ac = (slot & 3) << 2;
            const float4 v = *(const float4*)(A + (size_t)(bm + arow) * K + k0 + ac);
            As[ac + 0][arow] = v.x;
            As[ac + 1][arow] = v.y;
            As[ac + 2][arow] = v.z;
            As[ac + 3][arow] = v.w;
        }
        #pragma unroll
        for (int r = 0; r < 2; r++) {
            int slot = tid + r * 256;
            int nr = slot >> 2;
            int kc = (slot & 3) << 2;
            const float4 v = *(const float4*)(B + (size_t)(bn + nr) * K + k0 + kc);
            Bs[kc + 0][nr] = v.x;
            Bs[kc + 1][nr] = v.y;
            Bs[kc + 2][nr] = v.z;
            Bs[kc + 3][nr] = v.w;
        }
        __syncthreads();
        #pragma unroll
        for (int kk = 0; kk < 16; kk++) {
            float ra[8], rb[8];
            *(float4*)&ra[0] = *(const float4*)&As[kk][ty * 8];
            *(float4*)&ra[4] = *(const float4*)&As[kk][ty * 8 + 4];
            *(float4*)&rb[0] = *(const float4*)&Bs[kk][tx * 8];
            *(float4*)&rb[4] = *(const float4*)&Bs[kk][tx * 8 + 4];
            #pragma unroll
            for (int i = 0; i < 8; i++)
                #pragma unroll
                for (int j = 0; j < 8; j++) acc[i][j] += ra[i] * rb[j];
        }
        __syncthreads();
    }

    int row0 = bm + ty * 8, col0 = bn + tx * 8;
    #pragma unroll
    for (int i = 0; i < 8; i++)
        #pragma unroll
        for (int j = 0; j < 8; j++)
            out[(size_t)(row0 + i) * N + col0 + j] = acc[i][j];
}

// ---------------- launcher ----------------
extern "C" void kernel_launch(void* const* d_in, const int* in_sizes, int n_in,
                              void* d_out, int out_size) {
    const int*   x     = (const int*)d_in[0];
    const float* embed = (const float*)d_in[1];
    const float* kpar  = (const float*)d_in[2];
    const float* gamma = (const float*)d_in[3];
    const float* beta  = (const float*)d_in[4];
    const float* W1    = (const float*)d_in[5];
    const float* b1    = (const float*)d_in[6];
    const float* W2    = (const float*)d_in[7];
    const float* b2    = (const float*)d_in[8];
    float* out = (float*)d_out;

    cudaFuncSetAttribute(gemm1_bf16, cudaFuncAttributeMaxDynamicSharedMemorySize, GSMEM);
    cudaFuncSetAttribute(gemm2_bf16, cudaFuncAttributeMaxDynamicSharedMemorySize, GSMEM);

    dim3 sg(BB, NCH);

    embed_cumprod_kernel<<<NTOK / 8, 256>>>(x, embed);
    split_weights_kernel<<<(3 * DD * HH) / 256, 256>>>(W1, W2);
    boundA_kernel<<<sg, DD>>>();
    boundB_kernel<<<BB, DD>>>();
    boundC_kernel<<<sg, DD>>>();

    for (int l = 0; l < 3; l++) {
        scanA_kernel<<<sg, DD>>>(kpar, l);
        scanB_kernel<<<BB, DD>>>(kpar, l);
        magdecayC_kernel<<<sg, DD>>>(kpar, l);
        layernorm_kernel<<<NTOK, 128>>>(gamma + l * DD, beta + l * DD);
        gemm1_bf16<<<dim3(HH / 128, NTOK / 128), 256, GSMEM>>>(b1 + l * HH, l);
        gemm2_bf16<<<dim3(DD / 128, NTOK / 128), 256, GSMEM>>>(b2 + l * DD, l);
    }
    gemm_out_kernel<<<dim3(VV / 128, NTOK / 128), 256>>>(embed, out);
}

// round 10
// speedup vs baseline: 1.5624x; 1.4321x over previous
#include <cuda_runtime.h>
#include <cuda_fp16.h>
#include <math.h>
#include <stdint.h>

#define BB 4
#define TT 2048
#define DD 512
#define HH 2048
#define VV 256
#define NTOK (BB*TT)   // 8192
#define CS 64
#define NCH (TT/CS)

// ---------------- scratch ----------------
__device__ __align__(128) float g_h[NTOK*DD];
__device__ __align__(128) float g_s1[NTOK*DD];
__device__ __align__(128) float g_partA[BB*NCH*DD];
__device__ __align__(128) float g_partB[BB*NCH*DD];
__device__ __align__(128) __half g_s2[NTOK*DD];                 // LN out, fp16
__device__ __align__(128) __half g_act[(size_t)NTOK*HH];        // GELU out, fp16
__device__ __align__(128) __half g_w1h[3*DD*HH];
__device__ __align__(128) __half g_w1l[3*DD*HH];
__device__ __align__(128) __half g_w2h[3*DD*HH];
__device__ __align__(128) __half g_w2l[3*DD*HH];

__device__ __forceinline__ float softplus_lambda(float kv) {
    float sp = (kv > 0.f) ? (kv + log1pf(expf(-kv))) : log1pf(expf(kv));
    return expf(-sp);
}

// ---------------- weight split prepass (fp16 hi/lo, exact to 2^-22) --------
__global__ void split_weights_kernel(const float* __restrict__ W1, const float* __restrict__ W2) {
    size_t i = (size_t)blockIdx.x * blockDim.x + threadIdx.x;
    float v1 = W1[i];
    __half h1 = __float2half(v1);
    g_w1h[i] = h1;
    g_w1l[i] = __float2half(v1 - __half2float(h1));
    float v2 = W2[i];
    __half h2 = __float2half(v2);
    g_w2h[i] = h2;
    g_w2l[i] = __float2half(v2 - __half2float(h2));
}

// ---------------- fused embed gather + tanh(cumprod) (warp per token) ------
__global__ void embed_cumprod_kernel(const int* __restrict__ x, const float* __restrict__ embed) {
    int w = threadIdx.x >> 5;
    int lane = threadIdx.x & 31;
    int tok = blockIdx.x * 8 + w;
    const float* src = embed + (size_t)x[tok] * DD;
    size_t base = (size_t)tok * DD + lane * 16;
    float v[16];
    #pragma unroll
    for (int j = 0; j < 4; j++)
        *(float4*)&v[j * 4] = *(const float4*)(src + lane * 16 + j * 4);
    float c[16];
    float run = 1.f;
    #pragma unroll
    for (int j = 0; j < 16; j++) {
        run *= v[j];
        c[j] = run;
    }
    float incl = run;
    #pragma unroll
    for (int off = 1; off < 32; off <<= 1) {
        float p = __shfl_up_sync(0xffffffffu, incl, off);
        if (lane >= off) incl *= p;
    }
    float pre = __shfl_up_sync(0xffffffffu, incl, 1);
    if (lane == 0) pre = 1.f;
    #pragma unroll
    for (int j = 0; j < 4; j++) {
        *(float4*)&g_h[base + j * 4] = *(const float4*)&v[j * 4];
        float4 o;
        o.x = tanhf(pre * c[j * 4 + 0]);
        o.y = tanhf(pre * c[j * 4 + 1]);
        o.z = tanhf(pre * c[j * 4 + 2]);
        o.w = tanhf(pre * c[j * 4 + 3]);
        *(float4*)&g_s1[base + j * 4] = o;
    }
}

// ============= boundary scan ================================================
__global__ void boundA_kernel() {
    int b = blockIdx.x, ch = blockIdx.y, d = threadIdx.x;
    size_t base = ((size_t)b * TT + ch * CS) * DD + d;
    float s = 0.f;
    #pragma unroll 8
    for (int i = 0; i < CS; i++) s += g_s1[base + (size_t)i * DD];
    g_partA[((size_t)b * NCH + ch) * DD + d] = s;
}

__global__ void boundB_kernel() {
    int b = blockIdx.x, d = threadIdx.x;
    float c = 0.f;
    for (int ch = 0; ch < NCH; ch++) {
        size_t idx = ((size_t)b * NCH + ch) * DD + d;
        float v = g_partA[idx];
        g_partA[idx] = c;
        c += v;
    }
}

__global__ void boundC_kernel() {
    int b = blockIdx.x, ch = blockIdx.y, d = threadIdx.x;
    size_t base = ((size_t)b * TT + ch * CS) * DD + d;
    float acc = g_partA[((size_t)b * NCH + ch) * DD + d];
    #pragma unroll 4
    for (int i = 0; i < CS; i++) {
        size_t idx = base + (size_t)i * DD;
        acc += g_s1[idx];
        g_h[idx] = g_h[idx] * (1.0f + acc);
    }
}

// ============= per-layer scans =============================================
__global__ void scanA_kernel(const float* __restrict__ kpar, int l) {
    int b = blockIdx.x, ch = blockIdx.y, d = threadIdx.x;
    float lam = softplus_lambda(kpar[l]);
    size_t base = ((size_t)b * TT + ch * CS) * DD + d;
    float s = 0.f, loc = 0.f;
    #pragma unroll 4
    for (int i = 0; i < CS; i++) {
        float v = g_h[base + (size_t)i * DD];
        s += v;
        loc = v + lam * loc;
    }
    size_t pidx = ((size_t)b * NCH + ch) * DD + d;
    g_partA[pidx] = s;
    g_partB[pidx] = loc;
}

__global__ void scanB_kernel(const float* __restrict__ kpar, int l) {
    int b = blockIdx.x, d = threadIdx.x;
    float lam = softplus_lambda(kpar[l]);
    float lamCS = powf(lam, (float)CS);
    float c1 = 0.f, c2 = 0.f;
    for (int ch = 0; ch < NCH; ch++) {
        size_t idx = ((size_t)b * NCH + ch) * DD + d;
        float a = g_partA[idx];
        float v = g_partB[idx];
        g_partA[idx] = c1;
        g_partB[idx] = c2;
        c1 += a;
        c2 = v + lamCS * c2;
    }
}

// ======== fused mag + decay-ctx ============================================
__global__ void magdecayC_kernel(const float* __restrict__ kpar, int l) {
    __shared__ float accw[CS][17];
    __shared__ float smag[CS];
    int b = blockIdx.x, ch = blockIdx.y;
    int d = threadIdx.x;
    int lane = d & 31, wid = d >> 5;
    int t0 = ch * CS;
    size_t base = ((size_t)b * TT + t0) * DD + d;
    float acc = g_partA[((size_t)b * NCH + ch) * DD + d];
    float hp = (t0 > 0) ? g_h[base - DD] : 0.f;
    #pragma unroll 4
    for (int i = 0; i < CS; i++) {
        float v = g_h[base + (size_t)i * DD];
        acc += v;
        float diff = acc - hp;
        float sq = diff * diff;
        #pragma unroll
        for (int o = 16; o; o >>= 1) sq += __shfl_down_sync(0xffffffffu, sq, o);
        if (lane == 0) accw[i][wid] = sq;
        hp = v;
    }
    __syncthreads();
    if (d < CS) {
        float s = 0.f;
        #pragma unroll
        for (int w = 0; w < 16; w++) s += accw[d][w];
        smag[d] = sqrtf(s);
    }
    __syncthreads();
    float lam = softplus_lambda(kpar[l]);
    float S = g_partB[((size_t)b * NCH + ch) * DD + d];
    #pragma unroll 4
    for (int i = 0; i < CS; i++) {
        size_t idx = base + (size_t)i * DD;
        S = g_h[idx] + lam * S;
        g_s1[idx] = fabsf(smag[i] * S);
    }
}

// ---------------- block reduction ----------------
__device__ __forceinline__ float block_reduce(float v, float* sh) {
    int lane = threadIdx.x & 31, wid = threadIdx.x >> 5;
    #pragma unroll
    for (int o = 16; o; o >>= 1) v += __shfl_down_sync(0xffffffffu, v, o);
    if (lane == 0) sh[wid] = v;
    __syncthreads();
    float r = 0.f;
    if (threadIdx.x < (blockDim.x >> 5)) r = sh[threadIdx.x];
    if (wid == 0) {
        #pragma unroll
        for (int o = 16; o; o >>= 1) r += __shfl_down_sync(0xffffffffu, r, o);
        if (lane == 0) sh[0] = r;
    }
    __syncthreads();
    r = sh[0];
    __syncthreads();
    return r;
}

// ---------------- layernorm -> fp16 s2 ----------------
__global__ void layernorm_kernel(const float* __restrict__ gamma, const float* __restrict__ beta) {
    __shared__ float row[DD];
    __shared__ float sh[32];
    int tok = blockIdx.x;
    size_t base = (size_t)tok * DD;
    float s = 0.f;
    for (int d = threadIdx.x; d < DD; d += blockDim.x) {
        float v = g_s1[base + d];
        row[d] = v;
        s += v;
    }
    s = block_reduce(s, sh);
    float mu = s * (1.0f / DD);
    float q = 0.f;
    for (int d = threadIdx.x; d < DD; d += blockDim.x) {
        float v = row[d] - mu;
        q += v * v;
    }
    q = block_reduce(q, sh);
    float rstd = rsqrtf(q * (1.0f / DD) + 1e-3f);
    for (int d = threadIdx.x; d < DD; d += blockDim.x) {
        float y = (row[d] - mu) * rstd * gamma[d] + beta[d];
        g_s2[base + d] = __float2half(y);
    }
}

// ============ fp16 2-term tensor-core GEMM (A exact-quantized, B hi/lo) ====
// 128x128 block tile, 8 warps (2m x 4n, warp tile 64x32), register staging,
// double-buffered K16 stages, 2 CTAs/SM.
#define AROWB 48
#define A_TILE_B (128*AROWB)           // 6144
#define BROWB 272                      // 128 cols * 2B + 16 pad
#define B_TILE_B (16*BROWB)            // 4352
#define SM_A_BYTES (2*A_TILE_B)        // 12288 (2 buf, single precision level)
#define SM_B_BYTES (4*B_TILE_B)        // 17408 (2 buf x hi/lo)
#define GSMEM (SM_A_BYTES + SM_B_BYTES)  // 29696

#define LDSM4(r0,r1,r2,r3,addr) \
    asm volatile("ldmatrix.sync.aligned.m8n8.x4.shared.b16 {%0,%1,%2,%3},[%4];" \
                 : "=r"(r0),"=r"(r1),"=r"(r2),"=r"(r3) : "r"(addr))
#define LDSM4T(r0,r1,r2,r3,addr) \
    asm volatile("ldmatrix.sync.aligned.m8n8.x4.trans.shared.b16 {%0,%1,%2,%3},[%4];" \
                 : "=r"(r0),"=r"(r1),"=r"(r2),"=r"(r3) : "r"(addr))
#define MMA_F16(c,a,b0,b1) \
    asm volatile("mma.sync.aligned.m16n8k16.row.col.f32.f16.f16.f32 " \
                 "{%0,%1,%2,%3},{%4,%5,%6,%7},{%8,%9},{%0,%1,%2,%3};" \
                 : "+f"(c[0]),"+f"(c[1]),"+f"(c[2]),"+f"(c[3]) \
                 : "r"(a[0]),"r"(a[1]),"r"(a[2]),"r"(a[3]),"r"(b0),"r"(b1))

struct StageRegs { uint4 ah, bh, bl; };

__device__ __forceinline__ void ldg_tile(const __half* __restrict__ A,
                                         const __half* __restrict__ Bh,
                                         const __half* __restrict__ Bl,
                                         int bm, int bn, int k0, int K, int N,
                                         int tid, StageRegs& r) {
    int arow = tid >> 1, aseg = tid & 1;
    r.ah = *(const uint4*)(A + (size_t)(bm + arow) * K + k0 + aseg * 8);
    int k = tid >> 4, ng = tid & 15;           // 16 k-rows x 16 col-groups
    size_t bbase = (size_t)(k0 + k) * N + bn + ng * 8;
    r.bh = *(const uint4*)(Bh + bbase);
    r.bl = *(const uint4*)(Bl + bbase);
}

__device__ __forceinline__ void sts_tile(char* sbase, int p, int tid, const StageRegs& r) {
    int arow = tid >> 1, aseg = tid & 1;
    *(uint4*)(sbase + p * A_TILE_B + arow * AROWB + aseg * 16) = r.ah;
    int k = tid >> 4, ng = tid & 15;
    char* Bp = sbase + SM_A_BYTES + p * (2 * B_TILE_B);
    *(uint4*)(Bp + k * BROWB + ng * 16) = r.bh;
    *(uint4*)(Bp + B_TILE_B + k * BROWB + ng * 16) = r.bl;
}

__device__ __forceinline__ float gelu_exact(float c) {
    return 0.5f * c * (1.0f + erff(c * 0.70710678118654752f));
}

// EPI 0: bias+GELU -> fp16 Ch.  EPI 1: bias + accumulate into Cf.
template <int EPI>
__device__ __forceinline__ void gemm_f16x2(const __half* __restrict__ A,
                                           const __half* __restrict__ Bh,
                                           const __half* __restrict__ Bl,
                                           const float* __restrict__ bias,
                                           float* __restrict__ Cf,
                                           __half* __restrict__ Ch,
                                           int M, int N, int K) {
    extern __shared__ char smc[];
    const int bm = blockIdx.y * 128;
    const int bn = blockIdx.x * 128;
    const int tid = threadIdx.x;
    const int lane = tid & 31;
    const int wid = tid >> 5;
    const int wm = wid >> 2, wn = wid & 3;     // warp tile 64m x 32n
    const int g = lane >> 2, kq = lane & 3;
    const int lrow = lane & 7, lmat = lane >> 3;

    const uint32_t smem_u32 = (uint32_t)__cvta_generic_to_shared(smc);
    const uint32_t aoff = smem_u32 + (uint32_t)((wm * 64 + (lmat & 1) * 8 + lrow) * AROWB + (lmat >> 1) * 16);
    const uint32_t boff = smem_u32 + SM_A_BYTES +
                          (uint32_t)(((lmat & 1) * 8 + lrow) * BROWB + (wn * 32 + (lmat >> 1) * 8) * 2);

    float acc[4][4][4];
    #pragma unroll
    for (int mt = 0; mt < 4; mt++)
        #pragma unroll
        for (int nt = 0; nt < 4; nt++)
            #pragma unroll
            for (int r = 0; r < 4; r++) acc[mt][nt][r] = 0.f;

    const int KT = K >> 4;
    StageRegs sr;
    ldg_tile(A, Bh, Bl, bm, bn, 0, K, N, tid, sr);
    sts_tile(smc, 0, tid, sr);
    __syncthreads();

    for (int kt = 0; kt < KT; kt++) {
        const int p = kt & 1;
        const bool more = (kt + 1 < KT);
        if (more) ldg_tile(A, Bh, Bl, bm, bn, (kt + 1) << 4, K, N, tid, sr);

        const uint32_t aB = aoff + p * A_TILE_B;
        const uint32_t bB = boff + p * (2 * B_TILE_B);
        uint32_t aH[4][4];
        #pragma unroll
        for (int mt = 0; mt < 4; mt++)
            LDSM4(aH[mt][0], aH[mt][1], aH[mt][2], aH[mt][3], aB + mt * (16 * AROWB));
        #pragma unroll
        for (int ntp = 0; ntp < 2; ntp++) {
            uint32_t bh[4], bl[4];
            LDSM4T(bh[0], bh[1], bh[2], bh[3], bB + ntp * 32);
            LDSM4T(bl[0], bl[1], bl[2], bl[3], bB + ntp * 32 + B_TILE_B);
            #pragma unroll
            for (int w = 0; w < 2; w++) {
                const int nt = 2 * ntp + w;
                #pragma unroll
                for (int mt = 0; mt < 4; mt++) {
                    MMA_F16(acc[mt][nt], aH[mt], bl[2 * w], bl[2 * w + 1]);
                    MMA_F16(acc[mt][nt], aH[mt], bh[2 * w], bh[2 * w + 1]);
                }
            }
        }
        if (more) sts_tile(smc, p ^ 1, tid, sr);
        __syncthreads();
    }

    // epilogue
    #pragma unroll
    for (int mt = 0; mt < 4; mt++) {
        const int m0 = bm + wm * 64 + mt * 16 + g;
        #pragma unroll
        for (int nt = 0; nt < 4; nt++) {
            const int n0 = bn + wn * 32 + nt * 8 + kq * 2;
            const float b0 = bias[n0], b1 = bias[n0 + 1];
            if (EPI == 0) {
                float v0 = gelu_exact(acc[mt][nt][0] + b0);
                float v1 = gelu_exact(acc[mt][nt][1] + b1);
                float v2 = gelu_exact(acc[mt][nt][2] + b0);
                float v3 = gelu_exact(acc[mt][nt][3] + b1);
                __half2 p01 = __floats2half2_rn(v0, v1);
                __half2 p23 = __floats2half2_rn(v2, v3);
                size_t i0 = ((size_t)m0 * N + n0) >> 1;
                size_t i1 = ((size_t)(m0 + 8) * N + n0) >> 1;
                ((__half2*)Ch)[i0] = p01;
                ((__half2*)Ch)[i1] = p23;
            } else {
                float2* p0 = (float2*)&Cf[(size_t)m0 * N + n0];
                float2* p1 = (float2*)&Cf[(size_t)(m0 + 8) * N + n0];
                float2 o0 = *p0, o1 = *p1;
                o0.x += acc[mt][nt][0] + b0;
                o0.y += acc[mt][nt][1] + b1;
                o1.x += acc[mt][nt][2] + b0;
                o1.y += acc[mt][nt][3] + b1;
                *p0 = o0;
                *p1 = o1;
            }
        }
    }
}

__global__ void __launch_bounds__(256, 2) gemm1_f16(const float* __restrict__ b1, int l) {
    gemm_f16x2<0>(g_s2, g_w1h + (size_t)l * DD * HH, g_w1l + (size_t)l * DD * HH,
                  b1, nullptr, g_act, NTOK, HH, DD);
}
__global__ void __launch_bounds__(256, 2) gemm2_f16(const float* __restrict__ b2, int l) {
    gemm_f16x2<1>(g_act, g_w2h + (size_t)l * DD * HH, g_w2l + (size_t)l * DD * HH,
                  b2, g_h, nullptr, NTOK, DD, HH);
}

// ---------------- fp32 SGEMM for output projection --------------------------
__global__ void __launch_bounds__(256) gemm_out_kernel(const float* __restrict__ embed,
                                                       float* __restrict__ out) {
    __shared__ float As[16][128];
    __shared__ float Bs[16][132];
    const float* A = g_h;
    const float* B = embed;
    const int N = VV, K = DD;
    const int bm = blockIdx.y * 128, bn = blockIdx.x * 128;
    const int tid = threadIdx.x;
    const int ty = tid >> 4, tx = tid & 15;
    float acc[8][8];
    #pragma unroll
    for (int i = 0; i < 8; i++)
        #pragma unroll
        for (int j = 0; j < 8; j++) acc[i][j] = 0.f;

    for (int k0 = 0; k0 < K; k0 += 16) {
        #pragma unroll
        for (int r = 0; r < 2; r++) {
            int slot = tid + r * 256;
            int arow = slot >> 2;
            int ac = (slot & 3) << 2;
            const float4 v = *(const float4*)(A + (size_t)(bm + arow) * K + k0 + ac);
            As[ac + 0][arow] = v.x;
            As[ac + 1][arow] = v.y;
            As[ac + 2][arow] = v.z;
            As[ac + 3][arow] = v.w;
        }
        #pragma unroll
        for (int r = 0; r < 2; r++) {
            int slot = tid + r * 256;
            int nr = slot >> 2;
            int kc = (slot & 3) << 2;
            const float4 v = *(const float4*)(B + (size_t)(bn + nr) * K + k0 + kc);
            Bs[kc + 0][nr] = v.x;
            Bs[kc + 1][nr] = v.y;
            Bs[kc + 2][nr] = v.z;
            Bs[kc + 3][nr] = v.w;
        }
        __syncthreads();
        #pragma unroll
        for (int kk = 0; kk < 16; kk++) {
            float ra[8], rb[8];
            *(float4*)&ra[0] = *(const float4*)&As[kk][ty * 8];
            *(float4*)&ra[4] = *(const float4*)&As[kk][ty * 8 + 4];
            *(float4*)&rb[0] = *(const float4*)&Bs[kk][tx * 8];
            *(float4*)&rb[4] = *(const float4*)&Bs[kk][tx * 8 + 4];
            #pragma unroll
            for (int i = 0; i < 8; i++)
                #pragma unroll
                for (int j = 0; j < 8; j++) acc[i][j] += ra[i] * rb[j];
        }
        __syncthreads();
    }

    int row0 = bm + ty * 8, col0 = bn + tx * 8;
    #pragma unroll
    for (int i = 0; i < 8; i++)
        #pragma unroll
        for (int j = 0; j < 8; j++)
            out[(size_t)(row0 + i) * N + col0 + j] = acc[i][j];
}

// ---------------- launcher ----------------
extern "C" void kernel_launch(void* const* d_in, const int* in_sizes, int n_in,
                              void* d_out, int out_size) {
    const int*   x     = (const int*)d_in[0];
    const float* embed = (const float*)d_in[1];
    const float* kpar  = (const float*)d_in[2];
    const float* gamma = (const float*)d_in[3];
    const float* beta  = (const float*)d_in[4];
    const float* W1    = (const float*)d_in[5];
    const float* b1    = (const float*)d_in[6];
    const float* W2    = (const float*)d_in[7];
    const float* b2    = (const float*)d_in[8];
    float* out = (float*)d_out;

    cudaFuncSetAttribute(gemm1_f16, cudaFuncAttributeMaxDynamicSharedMemorySize, GSMEM);
    cudaFuncSetAttribute(gemm2_f16, cudaFuncAttributeMaxDynamicSharedMemorySize, GSMEM);

    dim3 sg(BB, NCH);

    embed_cumprod_kernel<<<NTOK / 8, 256>>>(x, embed);
    split_weights_kernel<<<(3 * DD * HH) / 256, 256>>>(W1, W2);
    boundA_kernel<<<sg, DD>>>();
    boundB_kernel<<<BB, DD>>>();
    boundC_kernel<<<sg, DD>>>();

    for (int l = 0; l < 3; l++) {
        scanA_kernel<<<sg, DD>>>(kpar, l);
        scanB_kernel<<<BB, DD>>>(kpar, l);
        magdecayC_kernel<<<sg, DD>>>(kpar, l);
        layernorm_kernel<<<NTOK, 128>>>(gamma + l * DD, beta + l * DD);
        gemm1_f16<<<dim3(HH / 128, NTOK / 128), 256, GSMEM>>>(b1 + l * HH, l);
        gemm2_f16<<<dim3(DD / 128, NTOK / 128), 256, GSMEM>>>(b2 + l * DD, l);
    }
    gemm_out_kernel<<<dim3(VV / 128, NTOK / 128), 256>>>(embed, out);
}

// round 11
// speedup vs baseline: 1.6398x; 1.0495x over previous
#include <cuda_runtime.h>
#include <cuda_fp16.h>
#include <math.h>
#include <stdint.h>

#define BB 4
#define TT 2048
#define DD 512
#define HH 2048
#define VV 256
#define NTOK (BB*TT)   // 8192
#define CS 64
#define NCH (TT/CS)

// ---------------- scratch ----------------
__device__ __align__(128) float g_h[NTOK*DD];
__device__ __align__(128) float g_s1[NTOK*DD];
__device__ __align__(128) float g_partA[BB*NCH*DD];
__device__ __align__(128) float g_partB[BB*NCH*DD];
__device__ __align__(128) __half g_s2[NTOK*DD];                 // LN out, fp16
__device__ __align__(128) __half g_act[(size_t)NTOK*HH];        // GELU out, fp16
__device__ __align__(128) __half g_w1h[3*DD*HH];
__device__ __align__(128) __half g_w1l[3*DD*HH];
__device__ __align__(128) __half g_w2h[3*DD*HH];
__device__ __align__(128) __half g_w2l[3*DD*HH];

__device__ __forceinline__ float softplus_lambda(float kv) {
    float sp = (kv > 0.f) ? (kv + log1pf(expf(-kv))) : log1pf(expf(kv));
    return expf(-sp);
}

// ---------------- weight split prepass (fp16 hi/lo, exact to 2^-22) --------
__global__ void split_weights_kernel(const float* __restrict__ W1, const float* __restrict__ W2) {
    size_t i = (size_t)blockIdx.x * blockDim.x + threadIdx.x;
    float v1 = W1[i];
    __half h1 = __float2half(v1);
    g_w1h[i] = h1;
    g_w1l[i] = __float2half(v1 - __half2float(h1));
    float v2 = W2[i];
    __half h2 = __float2half(v2);
    g_w2h[i] = h2;
    g_w2l[i] = __float2half(v2 - __half2float(h2));
}

// ---------------- fused embed gather + tanh(cumprod) (warp per token) ------
__global__ void embed_cumprod_kernel(const int* __restrict__ x, const float* __restrict__ embed) {
    int w = threadIdx.x >> 5;
    int lane = threadIdx.x & 31;
    int tok = blockIdx.x * 8 + w;
    const float* src = embed + (size_t)x[tok] * DD;
    size_t base = (size_t)tok * DD + lane * 16;
    float v[16];
    #pragma unroll
    for (int j = 0; j < 4; j++)
        *(float4*)&v[j * 4] = *(const float4*)(src + lane * 16 + j * 4);
    float c[16];
    float run = 1.f;
    #pragma unroll
    for (int j = 0; j < 16; j++) {
        run *= v[j];
        c[j] = run;
    }
    float incl = run;
    #pragma unroll
    for (int off = 1; off < 32; off <<= 1) {
        float p = __shfl_up_sync(0xffffffffu, incl, off);
        if (lane >= off) incl *= p;
    }
    float pre = __shfl_up_sync(0xffffffffu, incl, 1);
    if (lane == 0) pre = 1.f;
    #pragma unroll
    for (int j = 0; j < 4; j++) {
        *(float4*)&g_h[base + j * 4] = *(const float4*)&v[j * 4];
        float4 o;
        o.x = tanhf(pre * c[j * 4 + 0]);
        o.y = tanhf(pre * c[j * 4 + 1]);
        o.z = tanhf(pre * c[j * 4 + 2]);
        o.w = tanhf(pre * c[j * 4 + 3]);
        *(float4*)&g_s1[base + j * 4] = o;
    }
}

// ============= boundary scan ================================================
__global__ void boundA_kernel() {
    int b = blockIdx.x, ch = blockIdx.y, d = threadIdx.x;
    size_t base = ((size_t)b * TT + ch * CS) * DD + d;
    float s = 0.f;
    #pragma unroll 8
    for (int i = 0; i < CS; i++) s += g_s1[base + (size_t)i * DD];
    g_partA[((size_t)b * NCH + ch) * DD + d] = s;
}

__global__ void boundB_kernel() {
    int b = blockIdx.x, d = threadIdx.x;
    float c = 0.f;
    for (int ch = 0; ch < NCH; ch++) {
        size_t idx = ((size_t)b * NCH + ch) * DD + d;
        float v = g_partA[idx];
        g_partA[idx] = c;
        c += v;
    }
}

__global__ void boundC_kernel() {
    int b = blockIdx.x, ch = blockIdx.y, d = threadIdx.x;
    size_t base = ((size_t)b * TT + ch * CS) * DD + d;
    float acc = g_partA[((size_t)b * NCH + ch) * DD + d];
    #pragma unroll 4
    for (int i = 0; i < CS; i++) {
        size_t idx = base + (size_t)i * DD;
        acc += g_s1[idx];
        g_h[idx] = g_h[idx] * (1.0f + acc);
    }
}

// ============= per-layer scans =============================================
__global__ void scanA_kernel(const float* __restrict__ kpar, int l) {
    int b = blockIdx.x, ch = blockIdx.y, d = threadIdx.x;
    float lam = softplus_lambda(kpar[l]);
    size_t base = ((size_t)b * TT + ch * CS) * DD + d;
    float s = 0.f, loc = 0.f;
    #pragma unroll 4
    for (int i = 0; i < CS; i++) {
        float v = g_h[base + (size_t)i * DD];
        s += v;
        loc = v + lam * loc;
    }
    size_t pidx = ((size_t)b * NCH + ch) * DD + d;
    g_partA[pidx] = s;
    g_partB[pidx] = loc;
}

__global__ void scanB_kernel(const float* __restrict__ kpar, int l) {
    int b = blockIdx.x, d = threadIdx.x;
    float lam = softplus_lambda(kpar[l]);
    float lamCS = powf(lam, (float)CS);
    float c1 = 0.f, c2 = 0.f;
    for (int ch = 0; ch < NCH; ch++) {
        size_t idx = ((size_t)b * NCH + ch) * DD + d;
        float a = g_partA[idx];
        float v = g_partB[idx];
        g_partA[idx] = c1;
        g_partB[idx] = c2;
        c1 += a;
        c2 = v + lamCS * c2;
    }
}

// ======== fused mag + decay-ctx + layernorm -> fp16 s2 =====================
// ctx = mag*|S|; LN stats from scan-pass reductions:
//   mu = mag*sum|S|/D, var = mag^2*sumS2/D - mu^2.
// S parked in smem; ctx never materialized in gmem.
#define MLN_SMEM ((CS*DD + 3*CS*17 + 3*CS) * 4)   // ~145 KB

__global__ void __launch_bounds__(DD, 1) mag_ln_kernel(const float* __restrict__ kpar, int l,
                                                       const float* __restrict__ gamma,
                                                       const float* __restrict__ beta) {
    extern __shared__ float sm[];
    float* sS  = sm;                 // [CS][DD]
    float* aM  = sS + CS * DD;       // [CS][17]
    float* a1  = aM + CS * 17;
    float* a2  = a1 + CS * 17;
    float* smu = a2 + CS * 17;       // [CS]
    float* srs = smu + CS;
    float* smg = srs + CS;

    int b = blockIdx.x, ch = blockIdx.y;
    int d = threadIdx.x;
    int lane = d & 31, wd = d >> 5;
    int t0 = ch * CS;
    size_t base = ((size_t)b * TT + t0) * DD + d;
    float lam = softplus_lambda(kpar[l]);
    float acc = g_partA[((size_t)b * NCH + ch) * DD + d];
    float S = g_partB[((size_t)b * NCH + ch) * DD + d];
    float hp = (t0 > 0) ? g_h[base - DD] : 0.f;

    #pragma unroll 4
    for (int i = 0; i < CS; i++) {
        float v = g_h[base + (size_t)i * DD];
        acc += v;                       // hcum
        float diff = acc - hp;
        float sq = diff * diff;
        S = v + lam * S;                // decay scan
        sS[i * DD + d] = S;
        float u1 = fabsf(S);
        float u2 = S * S;
        #pragma unroll
        for (int o = 16; o; o >>= 1) {
            sq += __shfl_down_sync(0xffffffffu, sq, o);
            u1 += __shfl_down_sync(0xffffffffu, u1, o);
            u2 += __shfl_down_sync(0xffffffffu, u2, o);
        }
        if (lane == 0) {
            aM[i * 17 + wd] = sq;
            a1[i * 17 + wd] = u1;
            a2[i * 17 + wd] = u2;
        }
        hp = v;
    }
    __syncthreads();
    if (d < CS) {
        float sm_ = 0.f, s1_ = 0.f, s2_ = 0.f;
        #pragma unroll
        for (int w = 0; w < 16; w++) {
            sm_ += aM[d * 17 + w];
            s1_ += a1[d * 17 + w];
            s2_ += a2[d * 17 + w];
        }
        float mag = sqrtf(sm_);
        float mu = mag * s1_ * (1.0f / DD);
        float ex2 = mag * mag * s2_ * (1.0f / DD);
        float var = ex2 - mu * mu;
        smu[d] = mu;
        srs[d] = rsqrtf(var + 1e-3f);
        smg[d] = mag;
    }
    __syncthreads();
    float gm = gamma[d], bt = beta[d];
    #pragma unroll 4
    for (int i = 0; i < CS; i++) {
        float ctx = smg[i] * fabsf(sS[i * DD + d]);
        float y = (ctx - smu[i]) * srs[i] * gm + bt;
        g_s2[base + (size_t)i * DD] = __float2half(y);
    }
}

// ============ fp16 2-term tensor-core GEMM (A exact-quantized, B hi/lo) ====
// 128x128 block tile, 8 warps (2m x 4n, warp tile 64x32), register staging,
// double-buffered K16 stages, 2 CTAs/SM.  (byte-identical to R10)
#define AROWB 48
#define A_TILE_B (128*AROWB)           // 6144
#define BROWB 272                      // 128 cols * 2B + 16 pad
#define B_TILE_B (16*BROWB)            // 4352
#define SM_A_BYTES (2*A_TILE_B)        // 12288
#define SM_B_BYTES (4*B_TILE_B)        // 17408
#define GSMEM (SM_A_BYTES + SM_B_BYTES)  // 29696

#define LDSM4(r0,r1,r2,r3,addr) \
    asm volatile("ldmatrix.sync.aligned.m8n8.x4.shared.b16 {%0,%1,%2,%3},[%4];" \
                 : "=r"(r0),"=r"(r1),"=r"(r2),"=r"(r3) : "r"(addr))
#define LDSM4T(r0,r1,r2,r3,addr) \
    asm volatile("ldmatrix.sync.aligned.m8n8.x4.trans.shared.b16 {%0,%1,%2,%3},[%4];" \
                 : "=r"(r0),"=r"(r1),"=r"(r2),"=r"(r3) : "r"(addr))
#define MMA_F16(c,a,b0,b1) \
    asm volatile("mma.sync.aligned.m16n8k16.row.col.f32.f16.f16.f32 " \
                 "{%0,%1,%2,%3},{%4,%5,%6,%7},{%8,%9},{%0,%1,%2,%3};" \
                 : "+f"(c[0]),"+f"(c[1]),"+f"(c[2]),"+f"(c[3]) \
                 : "r"(a[0]),"r"(a[1]),"r"(a[2]),"r"(a[3]),"r"(b0),"r"(b1))

struct StageRegs { uint4 ah, bh, bl; };

__device__ __forceinline__ void ldg_tile(const __half* __restrict__ A,
                                         const __half* __restrict__ Bh,
                                         const __half* __restrict__ Bl,
                                         int bm, int bn, int k0, int K, int N,
                                         int tid, StageRegs& r) {
    int arow = tid >> 1, aseg = tid & 1;
    r.ah = *(const uint4*)(A + (size_t)(bm + arow) * K + k0 + aseg * 8);
    int k = tid >> 4, ng = tid & 15;
    size_t bbase = (size_t)(k0 + k) * N + bn + ng * 8;
    r.bh = *(const uint4*)(Bh + bbase);
    r.bl = *(const uint4*)(Bl + bbase);
}

__device__ __forceinline__ void sts_tile(char* sbase, int p, int tid, const StageRegs& r) {
    int arow = tid >> 1, aseg = tid & 1;
    *(uint4*)(sbase + p * A_TILE_B + arow * AROWB + aseg * 16) = r.ah;
    int k = tid >> 4, ng = tid & 15;
    char* Bp = sbase + SM_A_BYTES + p * (2 * B_TILE_B);
    *(uint4*)(Bp + k * BROWB + ng * 16) = r.bh;
    *(uint4*)(Bp + B_TILE_B + k * BROWB + ng * 16) = r.bl;
}

__device__ __forceinline__ float gelu_exact(float c) {
    return 0.5f * c * (1.0f + erff(c * 0.70710678118654752f));
}

// EPI 0: bias+GELU -> fp16 Ch.  EPI 1: bias + accumulate into Cf.
template <int EPI>
__device__ __forceinline__ void gemm_f16x2(const __half* __restrict__ A,
                                           const __half* __restrict__ Bh,
                                           const __half* __restrict__ Bl,
                                           const float* __restrict__ bias,
                                           float* __restrict__ Cf,
                                           __half* __restrict__ Ch,
                                           int M, int N, int K) {
    extern __shared__ char smc[];
    const int bm = blockIdx.y * 128;
    const int bn = blockIdx.x * 128;
    const int tid = threadIdx.x;
    const int lane = tid & 31;
    const int wid = tid >> 5;
    const int wm = wid >> 2, wn = wid & 3;
    const int g = lane >> 2, kq = lane & 3;
    const int lrow = lane & 7, lmat = lane >> 3;

    const uint32_t smem_u32 = (uint32_t)__cvta_generic_to_shared(smc);
    const uint32_t aoff = smem_u32 + (uint32_t)((wm * 64 + (lmat & 1) * 8 + lrow) * AROWB + (lmat >> 1) * 16);
    const uint32_t boff = smem_u32 + SM_A_BYTES +
                          (uint32_t)(((lmat & 1) * 8 + lrow) * BROWB + (wn * 32 + (lmat >> 1) * 8) * 2);

    float acc[4][4][4];
    #pragma unroll
    for (int mt = 0; mt < 4; mt++)
        #pragma unroll
        for (int nt = 0; nt < 4; nt++)
            #pragma unroll
            for (int r = 0; r < 4; r++) acc[mt][nt][r] = 0.f;

    const int KT = K >> 4;
    StageRegs sr;
    ldg_tile(A, Bh, Bl, bm, bn, 0, K, N, tid, sr);
    sts_tile(smc, 0, tid, sr);
    __syncthreads();

    for (int kt = 0; kt < KT; kt++) {
        const int p = kt & 1;
        const bool more = (kt + 1 < KT);
        if (more) ldg_tile(A, Bh, Bl, bm, bn, (kt + 1) << 4, K, N, tid, sr);

        const uint32_t aB = aoff + p * A_TILE_B;
        const uint32_t bB = boff + p * (2 * B_TILE_B);
        uint32_t aH[4][4];
        #pragma unroll
        for (int mt = 0; mt < 4; mt++)
            LDSM4(aH[mt][0], aH[mt][1], aH[mt][2], aH[mt][3], aB + mt * (16 * AROWB));
        #pragma unroll
        for (int ntp = 0; ntp < 2; ntp++) {
            uint32_t bh[4], bl[4];
            LDSM4T(bh[0], bh[1], bh[2], bh[3], bB + ntp * 32);
            LDSM4T(bl[0], bl[1], bl[2], bl[3], bB + ntp * 32 + B_TILE_B);
            #pragma unroll
            for (int w = 0; w < 2; w++) {
                const int nt = 2 * ntp + w;
                #pragma unroll
                for (int mt = 0; mt < 4; mt++) {
                    MMA_F16(acc[mt][nt], aH[mt], bl[2 * w], bl[2 * w + 1]);
                    MMA_F16(acc[mt][nt], aH[mt], bh[2 * w], bh[2 * w + 1]);
                }
            }
        }
        if (more) sts_tile(smc, p ^ 1, tid, sr);
        __syncthreads();
    }

    // epilogue
    #pragma unroll
    for (int mt = 0; mt < 4; mt++) {
        const int m0 = bm + wm * 64 + mt * 16 + g;
        #pragma unroll
        for (int nt = 0; nt < 4; nt++) {
            const int n0 = bn + wn * 32 + nt * 8 + kq * 2;
            const float b0 = bias[n0], b1 = bias[n0 + 1];
            if (EPI == 0) {
                float v0 = gelu_exact(acc[mt][nt][0] + b0);
                float v1 = gelu_exact(acc[mt][nt][1] + b1);
                float v2 = gelu_exact(acc[mt][nt][2] + b0);
                float v3 = gelu_exact(acc[mt][nt][3] + b1);
                __half2 p01 = __floats2half2_rn(v0, v1);
                __half2 p23 = __floats2half2_rn(v2, v3);
                size_t i0 = ((size_t)m0 * N + n0) >> 1;
                size_t i1 = ((size_t)(m0 + 8) * N + n0) >> 1;
                ((__half2*)Ch)[i0] = p01;
                ((__half2*)Ch)[i1] = p23;
            } else {
                float2* p0 = (float2*)&Cf[(size_t)m0 * N + n0];
                float2* p1 = (float2*)&Cf[(size_t)(m0 + 8) * N + n0];
                float2 o0 = *p0, o1 = *p1;
                o0.x += acc[mt][nt][0] + b0;
                o0.y += acc[mt][nt][1] + b1;
                o1.x += acc[mt][nt][2] + b0;
                o1.y += acc[mt][nt][3] + b1;
                *p0 = o0;
                *p1 = o1;
            }
        }
    }
}

__global__ void __launch_bounds__(256, 2) gemm1_f16(const float* __restrict__ b1, int l) {
    gemm_f16x2<0>(g_s2, g_w1h + (size_t)l * DD * HH, g_w1l + (size_t)l * DD * HH,
                  b1, nullptr, g_act, NTOK, HH, DD);
}
__global__ void __launch_bounds__(256, 2) gemm2_f16(const float* __restrict__ b2, int l) {
    gemm_f16x2<1>(g_act, g_w2h + (size_t)l * DD * HH, g_w2l + (size_t)l * DD * HH,
                  b2, g_h, nullptr, NTOK, DD, HH);
}

// ---------------- fp32 SGEMM for output projection --------------------------
__global__ void __launch_bounds__(256) gemm_out_kernel(const float* __restrict__ embed,
                                                       float* __restrict__ out) {
    __shared__ float As[16][128];
    __shared__ float Bs[16][132];
    const float* A = g_h;
    const float* B = embed;
    const int N = VV, K = DD;
    const int bm = blockIdx.y * 128, bn = blockIdx.x * 128;
    const int tid = threadIdx.x;
    const int ty = tid >> 4, tx = tid & 15;
    float acc[8][8];
    #pragma unroll
    for (int i = 0; i < 8; i++)
        #pragma unroll
        for (int j = 0; j < 8; j++) acc[i][j] = 0.f;

    for (int k0 = 0; k0 < K; k0 += 16) {
        #pragma unroll
        for (int r = 0; r < 2; r++) {
            int slot = tid + r * 256;
            int arow = slot >> 2;
            int ac = (slot & 3) << 2;
            const float4 v = *(const float4*)(A + (size_t)(bm + arow) * K + k0 + ac);
            As[ac + 0][arow] = v.x;
            As[ac + 1][arow] = v.y;
            As[ac + 2][arow] = v.z;
            As[ac + 3][arow] = v.w;
        }
        #pragma unroll
        for (int r = 0; r < 2; r++) {
            int slot = tid + r * 256;
            int nr = slot >> 2;
            int kc = (slot & 3) << 2;
            const float4 v = *(const float4*)(B + (size_t)(bn + nr) * K + k0 + kc);
            Bs[kc + 0][nr] = v.x;
            Bs[kc + 1][nr] = v.y;
            Bs[kc + 2][nr] = v.z;
            Bs[kc + 3][nr] = v.w;
        }
        __syncthreads();
        #pragma unroll
        for (int kk = 0; kk < 16; kk++) {
            float ra[8], rb[8];
            *(float4*)&ra[0] = *(const float4*)&As[kk][ty * 8];
            *(float4*)&ra[4] = *(const float4*)&As[kk][ty * 8 + 4];
            *(float4*)&rb[0] = *(const float4*)&Bs[kk][tx * 8];
            *(float4*)&rb[4] = *(const float4*)&Bs[kk][tx * 8 + 4];
            #pragma unroll
            for (int i = 0; i < 8; i++)
                #pragma unroll
                for (int j = 0; j < 8; j++) acc[i][j] += ra[i] * rb[j];
        }
        __syncthreads();
    }

    int row0 = bm + ty * 8, col0 = bn + tx * 8;
    #pragma unroll
    for (int i = 0; i < 8; i++)
        #pragma unroll
        for (int j = 0; j < 8; j++)
            out[(size_t)(row0 + i) * N + col0 + j] = acc[i][j];
}

// ---------------- launcher ----------------
extern "C" void kernel_launch(void* const* d_in, const int* in_sizes, int n_in,
                              void* d_out, int out_size) {
    const int*   x     = (const int*)d_in[0];
    const float* embed = (const float*)d_in[1];
    const float* kpar  = (const float*)d_in[2];
    const float* gamma = (const float*)d_in[3];
    const float* beta  = (const float*)d_in[4];
    const float* W1    = (const float*)d_in[5];
    const float* b1    = (const float*)d_in[6];
    const float* W2    = (const float*)d_in[7];
    const float* b2    = (const float*)d_in[8];
    float* out = (float*)d_out;

    cudaFuncSetAttribute(gemm1_f16, cudaFuncAttributeMaxDynamicSharedMemorySize, GSMEM);
    cudaFuncSetAttribute(gemm2_f16, cudaFuncAttributeMaxDynamicSharedMemorySize, GSMEM);
    cudaFuncSetAttribute(mag_ln_kernel, cudaFuncAttributeMaxDynamicSharedMemorySize, MLN_SMEM);

    dim3 sg(BB, NCH);

    embed_cumprod_kernel<<<NTOK / 8, 256>>>(x, embed);
    split_weights_kernel<<<(3 * DD * HH) / 256, 256>>>(W1, W2);
    boundA_kernel<<<sg, DD>>>();
    boundB_kernel<<<BB, DD>>>();
    boundC_kernel<<<sg, DD>>>();

    for (int l = 0; l < 3; l++) {
        scanA_kernel<<<sg, DD>>>(kpar, l);
        scanB_kernel<<<BB, DD>>>(kpar, l);
        mag_ln_kernel<<<sg, DD, MLN_SMEM>>>(kpar, l, gamma + l * DD, beta + l * DD);
        gemm1_f16<<<dim3(HH / 128, NTOK / 128), 256, GSMEM>>>(b1 + l * HH, l);
        gemm2_f16<<<dim3(DD / 128, NTOK / 128), 256, GSMEM>>>(b2 + l * DD, l);
    }
    gemm_out_kernel<<<dim3(VV / 128, NTOK / 128), 256>>>(embed, out);
}

// round 12
// speedup vs baseline: 1.7643x; 1.0759x over previous
#include <cuda_runtime.h>
#include <cuda_fp16.h>
#include <math.h>
#include <stdint.h>

#define BB 4
#define TT 2048
#define DD 512
#define HH 2048
#define VV 256
#define NTOK (BB*TT)   // 8192
#define CS 64
#define NCH (TT/CS)

// ---------------- scratch ----------------
__device__ __align__(128) float g_h[NTOK*DD];
__device__ __align__(128) float g_s1[NTOK*DD];
__device__ __align__(128) float g_partA[BB*NCH*DD];
__device__ __align__(128) float g_partB[BB*NCH*DD];
__device__ __align__(128) __half g_s2[NTOK*DD];                 // LN out, fp16
__device__ __align__(128) __half g_act[(size_t)NTOK*HH];        // GELU out, fp16
__device__ __align__(128) __half g_w1h[3*DD*HH];
__device__ __align__(128) __half g_w1l[3*DD*HH];
__device__ __align__(128) __half g_w2h[3*DD*HH];

__device__ __forceinline__ float softplus_lambda(float kv) {
    float sp = (kv > 0.f) ? (kv + log1pf(expf(-kv))) : log1pf(expf(kv));
    return expf(-sp);
}

// ---------------- weight split prepass (W1 hi/lo fp16; W2 hi only) ---------
__global__ void split_weights_kernel(const float* __restrict__ W1, const float* __restrict__ W2) {
    size_t i = (size_t)blockIdx.x * blockDim.x + threadIdx.x;
    float v1 = W1[i];
    __half h1 = __float2half(v1);
    g_w1h[i] = h1;
    g_w1l[i] = __float2half(v1 - __half2float(h1));
    g_w2h[i] = __float2half(W2[i]);
}

// ---------------- fused embed gather + tanh(cumprod) (warp per token) ------
__global__ void embed_cumprod_kernel(const int* __restrict__ x, const float* __restrict__ embed) {
    int w = threadIdx.x >> 5;
    int lane = threadIdx.x & 31;
    int tok = blockIdx.x * 8 + w;
    const float* src = embed + (size_t)x[tok] * DD;
    size_t base = (size_t)tok * DD + lane * 16;
    float v[16];
    #pragma unroll
    for (int j = 0; j < 4; j++)
        *(float4*)&v[j * 4] = *(const float4*)(src + lane * 16 + j * 4);
    float c[16];
    float run = 1.f;
    #pragma unroll
    for (int j = 0; j < 16; j++) {
        run *= v[j];
        c[j] = run;
    }
    float incl = run;
    #pragma unroll
    for (int off = 1; off < 32; off <<= 1) {
        float p = __shfl_up_sync(0xffffffffu, incl, off);
        if (lane >= off) incl *= p;
    }
    float pre = __shfl_up_sync(0xffffffffu, incl, 1);
    if (lane == 0) pre = 1.f;
    #pragma unroll
    for (int j = 0; j < 4; j++) {
        *(float4*)&g_h[base + j * 4] = *(const float4*)&v[j * 4];
        float4 o;
        o.x = tanhf(pre * c[j * 4 + 0]);
        o.y = tanhf(pre * c[j * 4 + 1]);
        o.z = tanhf(pre * c[j * 4 + 2]);
        o.w = tanhf(pre * c[j * 4 + 3]);
        *(float4*)&g_s1[base + j * 4] = o;
    }
}

// ============= boundary scan ================================================
__global__ void boundA_kernel() {
    int b = blockIdx.x, ch = blockIdx.y, d = threadIdx.x;
    size_t base = ((size_t)b * TT + ch * CS) * DD + d;
    float s = 0.f;
    #pragma unroll 8
    for (int i = 0; i < CS; i++) s += g_s1[base + (size_t)i * DD];
    g_partA[((size_t)b * NCH + ch) * DD + d] = s;
}

__global__ void boundB_kernel() {
    int b = blockIdx.x, d = threadIdx.x;
    float c = 0.f;
    for (int ch = 0; ch < NCH; ch++) {
        size_t idx = ((size_t)b * NCH + ch) * DD + d;
        float v = g_partA[idx];
        g_partA[idx] = c;
        c += v;
    }
}

__global__ void boundC_kernel() {
    int b = blockIdx.x, ch = blockIdx.y, d = threadIdx.x;
    size_t base = ((size_t)b * TT + ch * CS) * DD + d;
    float acc = g_partA[((size_t)b * NCH + ch) * DD + d];
    #pragma unroll 4
    for (int i = 0; i < CS; i++) {
        size_t idx = base + (size_t)i * DD;
        acc += g_s1[idx];
        g_h[idx] = g_h[idx] * (1.0f + acc);
    }
}

// ============= per-layer scans =============================================
__global__ void scanA_kernel(const float* __restrict__ kpar, int l) {
    int b = blockIdx.x, ch = blockIdx.y, d = threadIdx.x;
    float lam = softplus_lambda(kpar[l]);
    size_t base = ((size_t)b * TT + ch * CS) * DD + d;
    float s = 0.f, loc = 0.f;
    #pragma unroll 4
    for (int i = 0; i < CS; i++) {
        float v = g_h[base + (size_t)i * DD];
        s += v;
        loc = v + lam * loc;
    }
    size_t pidx = ((size_t)b * NCH + ch) * DD + d;
    g_partA[pidx] = s;
    g_partB[pidx] = loc;
}

__global__ void scanB_kernel(const float* __restrict__ kpar, int l) {
    int b = blockIdx.x, d = threadIdx.x;
    float lam = softplus_lambda(kpar[l]);
    float lamCS = powf(lam, (float)CS);
    float c1 = 0.f, c2 = 0.f;
    for (int ch = 0; ch < NCH; ch++) {
        size_t idx = ((size_t)b * NCH + ch) * DD + d;
        float a = g_partA[idx];
        float v = g_partB[idx];
        g_partA[idx] = c1;
        g_partB[idx] = c2;
        c1 += a;
        c2 = v + lamCS * c2;
    }
}

// ======== fused mag + decay-ctx + layernorm -> fp16 s2 =====================
#define MLN_SMEM ((CS*DD + 3*CS*17 + 3*CS) * 4)

__global__ void __launch_bounds__(DD, 1) mag_ln_kernel(const float* __restrict__ kpar, int l,
                                                       const float* __restrict__ gamma,
                                                       const float* __restrict__ beta) {
    extern __shared__ float sm[];
    float* sS  = sm;
    float* aM  = sS + CS * DD;
    float* a1  = aM + CS * 17;
    float* a2  = a1 + CS * 17;
    float* smu = a2 + CS * 17;
    float* srs = smu + CS;
    float* smg = srs + CS;

    int b = blockIdx.x, ch = blockIdx.y;
    int d = threadIdx.x;
    int lane = d & 31, wd = d >> 5;
    int t0 = ch * CS;
    size_t base = ((size_t)b * TT + t0) * DD + d;
    float lam = softplus_lambda(kpar[l]);
    float acc = g_partA[((size_t)b * NCH + ch) * DD + d];
    float S = g_partB[((size_t)b * NCH + ch) * DD + d];
    float hp = (t0 > 0) ? g_h[base - DD] : 0.f;

    #pragma unroll 4
    for (int i = 0; i < CS; i++) {
        float v = g_h[base + (size_t)i * DD];
        acc += v;
        float diff = acc - hp;
        float sq = diff * diff;
        S = v + lam * S;
        sS[i * DD + d] = S;
        float u1 = fabsf(S);
        float u2 = S * S;
        #pragma unroll
        for (int o = 16; o; o >>= 1) {
            sq += __shfl_down_sync(0xffffffffu, sq, o);
            u1 += __shfl_down_sync(0xffffffffu, u1, o);
            u2 += __shfl_down_sync(0xffffffffu, u2, o);
        }
        if (lane == 0) {
            aM[i * 17 + wd] = sq;
            a1[i * 17 + wd] = u1;
            a2[i * 17 + wd] = u2;
        }
        hp = v;
    }
    __syncthreads();
    if (d < CS) {
        float sm_ = 0.f, s1_ = 0.f, s2_ = 0.f;
        #pragma unroll
        for (int w = 0; w < 16; w++) {
            sm_ += aM[d * 17 + w];
            s1_ += a1[d * 17 + w];
            s2_ += a2[d * 17 + w];
        }
        float mag = sqrtf(sm_);
        float mu = mag * s1_ * (1.0f / DD);
        float ex2 = mag * mag * s2_ * (1.0f / DD);
        float var = ex2 - mu * mu;
        smu[d] = mu;
        srs[d] = rsqrtf(var + 1e-3f);
        smg[d] = mag;
    }
    __syncthreads();
    float gm = gamma[d], bt = beta[d];
    #pragma unroll 4
    for (int i = 0; i < CS; i++) {
        float ctx = smg[i] * fabsf(sS[i * DD + d]);
        float y = (ctx - smu[i]) * srs[i] * gm + bt;
        g_s2[base + (size_t)i * DD] = __float2half(y);
    }
}

// ============ fp16 tensor-core GEMM =========================================
// 128x128 block tile, 8 warps (2m x 4n), register staging, double-buffered
// K16 stages, 2 CTAs/SM.  TERMS=2: B hi+lo (gemm1); TERMS=1: B hi only (gemm2).
// smem layout is identical for both (lo region unused when TERMS==1).
#define AROWB 48
#define A_TILE_B (128*AROWB)           // 6144
#define BROWB 272
#define B_TILE_B (16*BROWB)            // 4352
#define SM_A_BYTES (2*A_TILE_B)        // 12288
#define SM_B_BYTES (4*B_TILE_B)        // 17408
#define GSMEM (SM_A_BYTES + SM_B_BYTES)  // 29696

#define LDSM4(r0,r1,r2,r3,addr) \
    asm volatile("ldmatrix.sync.aligned.m8n8.x4.shared.b16 {%0,%1,%2,%3},[%4];" \
                 : "=r"(r0),"=r"(r1),"=r"(r2),"=r"(r3) : "r"(addr))
#define LDSM4T(r0,r1,r2,r3,addr) \
    asm volatile("ldmatrix.sync.aligned.m8n8.x4.trans.shared.b16 {%0,%1,%2,%3},[%4];" \
                 : "=r"(r0),"=r"(r1),"=r"(r2),"=r"(r3) : "r"(addr))
#define MMA_F16(c,a,b0,b1) \
    asm volatile("mma.sync.aligned.m16n8k16.row.col.f32.f16.f16.f32 " \
                 "{%0,%1,%2,%3},{%4,%5,%6,%7},{%8,%9},{%0,%1,%2,%3};" \
                 : "+f"(c[0]),"+f"(c[1]),"+f"(c[2]),"+f"(c[3]) \
                 : "r"(a[0]),"r"(a[1]),"r"(a[2]),"r"(a[3]),"r"(b0),"r"(b1))

struct StageRegs { uint4 ah, bh, bl; };

template <int TERMS>
__device__ __forceinline__ void ldg_tile(const __half* __restrict__ A,
                                         const __half* __restrict__ Bh,
                                         const __half* __restrict__ Bl,
                                         int bm, int bn, int k0, int K, int N,
                                         int tid, StageRegs& r) {
    int arow = tid >> 1, aseg = tid & 1;
    r.ah = *(const uint4*)(A + (size_t)(bm + arow) * K + k0 + aseg * 8);
    int k = tid >> 4, ng = tid & 15;
    size_t bbase = (size_t)(k0 + k) * N + bn + ng * 8;
    r.bh = *(const uint4*)(Bh + bbase);
    if (TERMS == 2) r.bl = *(const uint4*)(Bl + bbase);
}

template <int TERMS>
__device__ __forceinline__ void sts_tile(char* sbase, int p, int tid, const StageRegs& r) {
    int arow = tid >> 1, aseg = tid & 1;
    *(uint4*)(sbase + p * A_TILE_B + arow * AROWB + aseg * 16) = r.ah;
    int k = tid >> 4, ng = tid & 15;
    char* Bp = sbase + SM_A_BYTES + p * (2 * B_TILE_B);
    *(uint4*)(Bp + k * BROWB + ng * 16) = r.bh;
    if (TERMS == 2) *(uint4*)(Bp + B_TILE_B + k * BROWB + ng * 16) = r.bl;
}

__device__ __forceinline__ float gelu_exact(float c) {
    return 0.5f * c * (1.0f + erff(c * 0.70710678118654752f));
}

// EPI 0: bias+GELU -> fp16 Ch.  EPI 1: bias + accumulate into Cf.
template <int EPI, int TERMS>
__device__ __forceinline__ void gemm_f16(const __half* __restrict__ A,
                                         const __half* __restrict__ Bh,
                                         const __half* __restrict__ Bl,
                                         const float* __restrict__ bias,
                                         float* __restrict__ Cf,
                                         __half* __restrict__ Ch,
                                         int M, int N, int K) {
    extern __shared__ char smc[];
    const int bm = blockIdx.y * 128;
    const int bn = blockIdx.x * 128;
    const int tid = threadIdx.x;
    const int lane = tid & 31;
    const int wid = tid >> 5;
    const int wm = wid >> 2, wn = wid & 3;
    const int g = lane >> 2, kq = lane & 3;
    const int lrow = lane & 7, lmat = lane >> 3;

    const uint32_t smem_u32 = (uint32_t)__cvta_generic_to_shared(smc);
    const uint32_t aoff = smem_u32 + (uint32_t)((wm * 64 + (lmat & 1) * 8 + lrow) * AROWB + (lmat >> 1) * 16);
    const uint32_t boff = smem_u32 + SM_A_BYTES +
                          (uint32_t)(((lmat & 1) * 8 + lrow) * BROWB + (wn * 32 + (lmat >> 1) * 8) * 2);

    float acc[4][4][4];
    #pragma unroll
    for (int mt = 0; mt < 4; mt++)
        #pragma unroll
        for (int nt = 0; nt < 4; nt++)
            #pragma unroll
            for (int r = 0; r < 4; r++) acc[mt][nt][r] = 0.f;

    const int KT = K >> 4;
    StageRegs sr;
    ldg_tile<TERMS>(A, Bh, Bl, bm, bn, 0, K, N, tid, sr);
    sts_tile<TERMS>(smc, 0, tid, sr);
    __syncthreads();

    for (int kt = 0; kt < KT; kt++) {
        const int p = kt & 1;
        const bool more = (kt + 1 < KT);
        if (more) ldg_tile<TERMS>(A, Bh, Bl, bm, bn, (kt + 1) << 4, K, N, tid, sr);

        const uint32_t aB = aoff + p * A_TILE_B;
        const uint32_t bB = boff + p * (2 * B_TILE_B);
        uint32_t aH[4][4];
        #pragma unroll
        for (int mt = 0; mt < 4; mt++)
            LDSM4(aH[mt][0], aH[mt][1], aH[mt][2], aH[mt][3], aB + mt * (16 * AROWB));
        #pragma unroll
        for (int ntp = 0; ntp < 2; ntp++) {
            uint32_t bh[4];
            LDSM4T(bh[0], bh[1], bh[2], bh[3], bB + ntp * 32);
            if (TERMS == 2) {
                uint32_t bl[4];
                LDSM4T(bl[0], bl[1], bl[2], bl[3], bB + ntp * 32 + B_TILE_B);
                #pragma unroll
                for (int w = 0; w < 2; w++) {
                    const int nt = 2 * ntp + w;
                    #pragma unroll
                    for (int mt = 0; mt < 4; mt++) {
                        MMA_F16(acc[mt][nt], aH[mt], bl[2 * w], bl[2 * w + 1]);
                        MMA_F16(acc[mt][nt], aH[mt], bh[2 * w], bh[2 * w + 1]);
                    }
                }
            } else {
                #pragma unroll
                for (int w = 0; w < 2; w++) {
                    const int nt = 2 * ntp + w;
                    #pragma unroll
                    for (int mt = 0; mt < 4; mt++)
                        MMA_F16(acc[mt][nt], aH[mt], bh[2 * w], bh[2 * w + 1]);
                }
            }
        }
        if (more) sts_tile<TERMS>(smc, p ^ 1, tid, sr);
        __syncthreads();
    }

    // epilogue
    #pragma unroll
    for (int mt = 0; mt < 4; mt++) {
        const int m0 = bm + wm * 64 + mt * 16 + g;
        #pragma unroll
        for (int nt = 0; nt < 4; nt++) {
            const int n0 = bn + wn * 32 + nt * 8 + kq * 2;
            const float b0 = bias[n0], b1 = bias[n0 + 1];
            if (EPI == 0) {
                float v0 = gelu_exact(acc[mt][nt][0] + b0);
                float v1 = gelu_exact(acc[mt][nt][1] + b1);
                float v2 = gelu_exact(acc[mt][nt][2] + b0);
                float v3 = gelu_exact(acc[mt][nt][3] + b1);
                __half2 p01 = __floats2half2_rn(v0, v1);
                __half2 p23 = __floats2half2_rn(v2, v3);
                size_t i0 = ((size_t)m0 * N + n0) >> 1;
                size_t i1 = ((size_t)(m0 + 8) * N + n0) >> 1;
                ((__half2*)Ch)[i0] = p01;
                ((__half2*)Ch)[i1] = p23;
            } else {
                float2* p0 = (float2*)&Cf[(size_t)m0 * N + n0];
                float2* p1 = (float2*)&Cf[(size_t)(m0 + 8) * N + n0];
                float2 o0 = *p0, o1 = *p1;
                o0.x += acc[mt][nt][0] + b0;
                o0.y += acc[mt][nt][1] + b1;
                o1.x += acc[mt][nt][2] + b0;
                o1.y += acc[mt][nt][3] + b1;
                *p0 = o0;
                *p1 = o1;
            }
        }
    }
}

__global__ void __launch_bounds__(256, 2) gemm1_f16(const float* __restrict__ b1, int l) {
    gemm_f16<0, 2>(g_s2, g_w1h + (size_t)l * DD * HH, g_w1l + (size_t)l * DD * HH,
                   b1, nullptr, g_act, NTOK, HH, DD);
}
__global__ void __launch_bounds__(256, 2) gemm2_f16(const float* __restrict__ b2, int l) {
    gemm_f16<1, 1>(g_act, g_w2h + (size_t)l * DD * HH, nullptr,
                   b2, g_h, nullptr, NTOK, DD, HH);
}

// ---------------- fp32 SGEMM for output projection --------------------------
__global__ void __launch_bounds__(256) gemm_out_kernel(const float* __restrict__ embed,
                                                       float* __restrict__ out) {
    __shared__ float As[16][128];
    __shared__ float Bs[16][132];
    const float* A = g_h;
    const float* B = embed;
    const int N = VV, K = DD;
    const int bm = blockIdx.y * 128, bn = blockIdx.x * 128;
    const int tid = threadIdx.x;
    const int ty = tid >> 4, tx = tid & 15;
    float acc[8][8];
    #pragma unroll
    for (int i = 0; i < 8; i++)
        #pragma unroll
        for (int j = 0; j < 8; j++) acc[i][j] = 0.f;

    for (int k0 = 0; k0 < K; k0 += 16) {
        #pragma unroll
        for (int r = 0; r < 2; r++) {
            int slot = tid + r * 256;
            int arow = slot >> 2;
            int ac = (slot & 3) << 2;
            const float4 v = *(const float4*)(A + (size_t)(bm + arow) * K + k0 + ac);
            As[ac + 0][arow] = v.x;
            As[ac + 1][arow] = v.y;
            As[ac + 2][arow] = v.z;
            As[ac + 3][arow] = v.w;
        }
        #pragma unroll
        for (int r = 0; r < 2; r++) {
            int slot = tid + r * 256;
            int nr = slot >> 2;
            int kc = (slot & 3) << 2;
            const float4 v = *(const float4*)(B + (size_t)(bn + nr) * K + k0 + kc);
            Bs[kc + 0][nr] = v.x;
            Bs[kc + 1][nr] = v.y;
            Bs[kc + 2][nr] = v.z;
            Bs[kc + 3][nr] = v.w;
        }
        __syncthreads();
        #pragma unroll
        for (int kk = 0; kk < 16; kk++) {
            float ra[8], rb[8];
            *(float4*)&ra[0] = *(const float4*)&As[kk][ty * 8];
            *(float4*)&ra[4] = *(const float4*)&As[kk][ty * 8 + 4];
            *(float4*)&rb[0] = *(const float4*)&Bs[kk][tx * 8];
            *(float4*)&rb[4] = *(const float4*)&Bs[kk][tx * 8 + 4];
            #pragma unroll
            for (int i = 0; i < 8; i++)
                #pragma unroll
                for (int j = 0; j < 8; j++) acc[i][j] += ra[i] * rb[j];
        }
        __syncthreads();
    }

    int row0 = bm + ty * 8, col0 = bn + tx * 8;
    #pragma unroll
    for (int i = 0; i < 8; i++)
        #pragma unroll
        for (int j = 0; j < 8; j++)
            out[(size_t)(row0 + i) * N + col0 + j] = acc[i][j];
}

// ---------------- launcher ----------------
extern "C" void kernel_launch(void* const* d_in, const int* in_sizes, int n_in,
                              void* d_out, int out_size) {
    const int*   x     = (const int*)d_in[0];
    const float* embed = (const float*)d_in[1];
    const float* kpar  = (const float*)d_in[2];
    const float* gamma = (const float*)d_in[3];
    const float* beta  = (const float*)d_in[4];
    const float* W1    = (const float*)d_in[5];
    const float* b1    = (const float*)d_in[6];
    const float* W2    = (const float*)d_in[7];
    const float* b2    = (const float*)d_in[8];
    float* out = (float*)d_out;

    cudaFuncSetAttribute(gemm1_f16, cudaFuncAttributeMaxDynamicSharedMemorySize, GSMEM);
    cudaFuncSetAttribute(gemm2_f16, cudaFuncAttributeMaxDynamicSharedMemorySize, GSMEM);
    cudaFuncSetAttribute(mag_ln_kernel, cudaFuncAttributeMaxDynamicSharedMemorySize, MLN_SMEM);

    dim3 sg(BB, NCH);

    embed_cumprod_kernel<<<NTOK / 8, 256>>>(x, embed);
    split_weights_kernel<<<(3 * DD * HH) / 256, 256>>>(W1, W2);
    boundA_kernel<<<sg, DD>>>();
    boundB_kernel<<<BB, DD>>>();
    boundC_kernel<<<sg, DD>>>();

    for (int l = 0; l < 3; l++) {
        scanA_kernel<<<sg, DD>>>(kpar, l);
        scanB_kernel<<<BB, DD>>>(kpar, l);
        mag_ln_kernel<<<sg, DD, MLN_SMEM>>>(kpar, l, gamma + l * DD, beta + l * DD);
        gemm1_f16<<<dim3(HH / 128, NTOK / 128), 256, GSMEM>>>(b1 + l * HH, l);
        gemm2_f16<<<dim3(DD / 128, NTOK / 128), 256, GSMEM>>>(b2 + l * DD, l);
    }
    gemm_out_kernel<<<dim3(VV / 128, NTOK / 128), 256>>>(embed, out);
}

// round 13
// speedup vs baseline: 1.8560x; 1.0520x over previous
#include <cuda_runtime.h>
#include <cuda_fp16.h>
#include <math.h>
#include <stdint.h>

#define BB 4
#define TT 2048
#define DD 512
#define HH 2048
#define VV 256
#define NTOK (BB*TT)   // 8192
#define CS 64
#define NCH (TT/CS)

// ---------------- scratch ----------------
__device__ __align__(128) float g_h[NTOK*DD];
__device__ __align__(128) float g_s1[NTOK*DD];
__device__ __align__(128) float g_partA[BB*NCH*DD];
__device__ __align__(128) float g_partB[BB*NCH*DD];
__device__ __align__(128) __half g_s2[NTOK*DD];                 // LN out, fp16
__device__ __align__(128) __half g_act[(size_t)NTOK*HH];        // GELU out, fp16
__device__ __align__(128) __half g_hq[NTOK*DD];                 // final h, fp16
__device__ __align__(128) __half g_w1h[3*DD*HH];
__device__ __align__(128) __half g_w1l[3*DD*HH];
__device__ __align__(128) __half g_w2h[3*DD*HH];
__device__ __align__(128) __half g_eth[DD*VV];                  // embed^T hi
__device__ __align__(128) __half g_etl[DD*VV];                  // embed^T lo

__device__ __forceinline__ float softplus_lambda(float kv) {
    float sp = (kv > 0.f) ? (kv + log1pf(expf(-kv))) : log1pf(expf(kv));
    return expf(-sp);
}

// ---------------- weight split prepass (W1 hi/lo fp16; W2 hi only) ---------
__global__ void split_weights_kernel(const float* __restrict__ W1, const float* __restrict__ W2) {
    size_t i = (size_t)blockIdx.x * blockDim.x + threadIdx.x;
    float v1 = W1[i];
    __half h1 = __float2half(v1);
    g_w1h[i] = h1;
    g_w1l[i] = __float2half(v1 - __half2float(h1));
    g_w2h[i] = __float2half(W2[i]);
}

// ---------------- embed^T split prepass: E[VV][DD] -> embT[DD][VV] hi/lo ---
__global__ void embedT_split_kernel(const float* __restrict__ E) {
    __shared__ float t[32][33];
    int v0 = blockIdx.x * 32, d0 = blockIdx.y * 32;
    #pragma unroll
    for (int i = threadIdx.y; i < 32; i += 8)
        t[i][threadIdx.x] = E[(size_t)(v0 + i) * DD + d0 + threadIdx.x];
    __syncthreads();
    #pragma unroll
    for (int i = threadIdx.y; i < 32; i += 8) {
        float val = t[threadIdx.x][i];
        size_t idx = (size_t)(d0 + i) * VV + v0 + threadIdx.x;
        __half hh = __float2half(val);
        g_eth[idx] = hh;
        g_etl[idx] = __float2half(val - __half2float(hh));
    }
}

// ---------------- final h -> fp16 ----------------
__global__ void h2half_kernel() {
    size_t i = (size_t)blockIdx.x * blockDim.x + threadIdx.x;
    g_hq[i] = __float2half(g_h[i]);
}

// ---------------- fused embed gather + tanh(cumprod) (warp per token) ------
__global__ void embed_cumprod_kernel(const int* __restrict__ x, const float* __restrict__ embed) {
    int w = threadIdx.x >> 5;
    int lane = threadIdx.x & 31;
    int tok = blockIdx.x * 8 + w;
    const float* src = embed + (size_t)x[tok] * DD;
    size_t base = (size_t)tok * DD + lane * 16;
    float v[16];
    #pragma unroll
    for (int j = 0; j < 4; j++)
        *(float4*)&v[j * 4] = *(const float4*)(src + lane * 16 + j * 4);
    float c[16];
    float run = 1.f;
    #pragma unroll
    for (int j = 0; j < 16; j++) {
        run *= v[j];
        c[j] = run;
    }
    float incl = run;
    #pragma unroll
    for (int off = 1; off < 32; off <<= 1) {
        float p = __shfl_up_sync(0xffffffffu, incl, off);
        if (lane >= off) incl *= p;
    }
    float pre = __shfl_up_sync(0xffffffffu, incl, 1);
    if (lane == 0) pre = 1.f;
    #pragma unroll
    for (int j = 0; j < 4; j++) {
        *(float4*)&g_h[base + j * 4] = *(const float4*)&v[j * 4];
        float4 o;
        o.x = tanhf(pre * c[j * 4 + 0]);
        o.y = tanhf(pre * c[j * 4 + 1]);
        o.z = tanhf(pre * c[j * 4 + 2]);
        o.w = tanhf(pre * c[j * 4 + 3]);
        *(float4*)&g_s1[base + j * 4] = o;
    }
}

// ============= boundary scan ================================================
__global__ void boundA_kernel() {
    int b = blockIdx.x, ch = blockIdx.y, d = threadIdx.x;
    size_t base = ((size_t)b * TT + ch * CS) * DD + d;
    float s = 0.f;
    #pragma unroll 8
    for (int i = 0; i < CS; i++) s += g_s1[base + (size_t)i * DD];
    g_partA[((size_t)b * NCH + ch) * DD + d] = s;
}

__global__ void boundB_kernel() {
    int b = blockIdx.x, d = threadIdx.x;
    float c = 0.f;
    for (int ch = 0; ch < NCH; ch++) {
        size_t idx = ((size_t)b * NCH + ch) * DD + d;
        float v = g_partA[idx];
        g_partA[idx] = c;
        c += v;
    }
}

__global__ void boundC_kernel() {
    int b = blockIdx.x, ch = blockIdx.y, d = threadIdx.x;
    size_t base = ((size_t)b * TT + ch * CS) * DD + d;
    float acc = g_partA[((size_t)b * NCH + ch) * DD + d];
    #pragma unroll 4
    for (int i = 0; i < CS; i++) {
        size_t idx = base + (size_t)i * DD;
        acc += g_s1[idx];
        g_h[idx] = g_h[idx] * (1.0f + acc);
    }
}

// ============= per-layer scans =============================================
__global__ void scanA_kernel(const float* __restrict__ kpar, int l) {
    int b = blockIdx.x, ch = blockIdx.y, d = threadIdx.x;
    float lam = softplus_lambda(kpar[l]);
    size_t base = ((size_t)b * TT + ch * CS) * DD + d;
    float s = 0.f, loc = 0.f;
    #pragma unroll 4
    for (int i = 0; i < CS; i++) {
        float v = g_h[base + (size_t)i * DD];
        s += v;
        loc = v + lam * loc;
    }
    size_t pidx = ((size_t)b * NCH + ch) * DD + d;
    g_partA[pidx] = s;
    g_partB[pidx] = loc;
}

__global__ void scanB_kernel(const float* __restrict__ kpar, int l) {
    int b = blockIdx.x, d = threadIdx.x;
    float lam = softplus_lambda(kpar[l]);
    float lamCS = powf(lam, (float)CS);
    float c1 = 0.f, c2 = 0.f;
    for (int ch = 0; ch < NCH; ch++) {
        size_t idx = ((size_t)b * NCH + ch) * DD + d;
        float a = g_partA[idx];
        float v = g_partB[idx];
        g_partA[idx] = c1;
        g_partB[idx] = c2;
        c1 += a;
        c2 = v + lamCS * c2;
    }
}

// ======== fused mag + decay-ctx + layernorm -> fp16 s2 =====================
#define MLN_SMEM ((CS*DD + 3*CS*17 + 3*CS) * 4)

__global__ void __launch_bounds__(DD, 1) mag_ln_kernel(const float* __restrict__ kpar, int l,
                                                       const float* __restrict__ gamma,
                                                       const float* __restrict__ beta) {
    extern __shared__ float sm[];
    float* sS  = sm;
    float* aM  = sS + CS * DD;
    float* a1  = aM + CS * 17;
    float* a2  = a1 + CS * 17;
    float* smu = a2 + CS * 17;
    float* srs = smu + CS;
    float* smg = srs + CS;

    int b = blockIdx.x, ch = blockIdx.y;
    int d = threadIdx.x;
    int lane = d & 31, wd = d >> 5;
    int t0 = ch * CS;
    size_t base = ((size_t)b * TT + t0) * DD + d;
    float lam = softplus_lambda(kpar[l]);
    float acc = g_partA[((size_t)b * NCH + ch) * DD + d];
    float S = g_partB[((size_t)b * NCH + ch) * DD + d];
    float hp = (t0 > 0) ? g_h[base - DD] : 0.f;

    #pragma unroll 4
    for (int i = 0; i < CS; i++) {
        float v = g_h[base + (size_t)i * DD];
        acc += v;
        float diff = acc - hp;
        float sq = diff * diff;
        S = v + lam * S;
        sS[i * DD + d] = S;
        float u1 = fabsf(S);
        float u2 = S * S;
        #pragma unroll
        for (int o = 16; o; o >>= 1) {
            sq += __shfl_down_sync(0xffffffffu, sq, o);
            u1 += __shfl_down_sync(0xffffffffu, u1, o);
            u2 += __shfl_down_sync(0xffffffffu, u2, o);
        }
        if (lane == 0) {
            aM[i * 17 + wd] = sq;
            a1[i * 17 + wd] = u1;
            a2[i * 17 + wd] = u2;
        }
        hp = v;
    }
    __syncthreads();
    if (d < CS) {
        float sm_ = 0.f, s1_ = 0.f, s2_ = 0.f;
        #pragma unroll
        for (int w = 0; w < 16; w++) {
            sm_ += aM[d * 17 + w];
            s1_ += a1[d * 17 + w];
            s2_ += a2[d * 17 + w];
        }
        float mag = sqrtf(sm_);
        float mu = mag * s1_ * (1.0f / DD);
        float ex2 = mag * mag * s2_ * (1.0f / DD);
        float var = ex2 - mu * mu;
        smu[d] = mu;
        srs[d] = rsqrtf(var + 1e-3f);
        smg[d] = mag;
    }
    __syncthreads();
    float gm = gamma[d], bt = beta[d];
    #pragma unroll 4
    for (int i = 0; i < CS; i++) {
        float ctx = smg[i] * fabsf(sS[i * DD + d]);
        float y = (ctx - smu[i]) * srs[i] * gm + bt;
        g_s2[base + (size_t)i * DD] = __float2half(y);
    }
}

// ============ fp16 tensor-core GEMM =========================================
// 128x128 block tile, 8 warps (2m x 4n), register staging, double-buffered
// K16 stages, 2 CTAs/SM.  TERMS=2: B hi+lo; TERMS=1: B hi only.
// EPI 0: bias+GELU -> fp16 Ch.  EPI 1: bias+accum into Cf.  EPI 2: store Cf.
#define AROWB 48
#define A_TILE_B (128*AROWB)           // 6144
#define BROWB 272
#define B_TILE_B (16*BROWB)            // 4352
#define SM_A_BYTES (2*A_TILE_B)        // 12288
#define SM_B_BYTES (4*B_TILE_B)        // 17408
#define GSMEM (SM_A_BYTES + SM_B_BYTES)  // 29696

#define LDSM4(r0,r1,r2,r3,addr) \
    asm volatile("ldmatrix.sync.aligned.m8n8.x4.shared.b16 {%0,%1,%2,%3},[%4];" \
                 : "=r"(r0),"=r"(r1),"=r"(r2),"=r"(r3) : "r"(addr))
#define LDSM4T(r0,r1,r2,r3,addr) \
    asm volatile("ldmatrix.sync.aligned.m8n8.x4.trans.shared.b16 {%0,%1,%2,%3},[%4];" \
                 : "=r"(r0),"=r"(r1),"=r"(r2),"=r"(r3) : "r"(addr))
#define MMA_F16(c,a,b0,b1) \
    asm volatile("mma.sync.aligned.m16n8k16.row.col.f32.f16.f16.f32 " \
                 "{%0,%1,%2,%3},{%4,%5,%6,%7},{%8,%9},{%0,%1,%2,%3};" \
                 : "+f"(c[0]),"+f"(c[1]),"+f"(c[2]),"+f"(c[3]) \
                 : "r"(a[0]),"r"(a[1]),"r"(a[2]),"r"(a[3]),"r"(b0),"r"(b1))

struct StageRegs { uint4 ah, bh, bl; };

template <int TERMS>
__device__ __forceinline__ void ldg_tile(const __half* __restrict__ A,
                                         const __half* __restrict__ Bh,
                                         const __half* __restrict__ Bl,
                                         int bm, int bn, int k0, int K, int N,
                                         int tid, StageRegs& r) {
    int arow = tid >> 1, aseg = tid & 1;
    r.ah = *(const uint4*)(A + (size_t)(bm + arow) * K + k0 + aseg * 8);
    int k = tid >> 4, ng = tid & 15;
    size_t bbase = (size_t)(k0 + k) * N + bn + ng * 8;
    r.bh = *(const uint4*)(Bh + bbase);
    if (TERMS == 2) r.bl = *(const uint4*)(Bl + bbase);
}

template <int TERMS>
__device__ __forceinline__ void sts_tile(char* sbase, int p, int tid, const StageRegs& r) {
    int arow = tid >> 1, aseg = tid & 1;
    *(uint4*)(sbase + p * A_TILE_B + arow * AROWB + aseg * 16) = r.ah;
    int k = tid >> 4, ng = tid & 15;
    char* Bp = sbase + SM_A_BYTES + p * (2 * B_TILE_B);
    *(uint4*)(Bp + k * BROWB + ng * 16) = r.bh;
    if (TERMS == 2) *(uint4*)(Bp + B_TILE_B + k * BROWB + ng * 16) = r.bl;
}

__device__ __forceinline__ float gelu_exact(float c) {
    return 0.5f * c * (1.0f + erff(c * 0.70710678118654752f));
}

template <int EPI, int TERMS>
__device__ __forceinline__ void gemm_f16(const __half* __restrict__ A,
                                         const __half* __restrict__ Bh,
                                         const __half* __restrict__ Bl,
                                         const float* __restrict__ bias,
                                         float* __restrict__ Cf,
                                         __half* __restrict__ Ch,
                                         int M, int N, int K) {
    extern __shared__ char smc[];
    const int bm = blockIdx.y * 128;
    const int bn = blockIdx.x * 128;
    const int tid = threadIdx.x;
    const int lane = tid & 31;
    const int wid = tid >> 5;
    const int wm = wid >> 2, wn = wid & 3;
    const int g = lane >> 2, kq = lane & 3;
    const int lrow = lane & 7, lmat = lane >> 3;

    const uint32_t smem_u32 = (uint32_t)__cvta_generic_to_shared(smc);
    const uint32_t aoff = smem_u32 + (uint32_t)((wm * 64 + (lmat & 1) * 8 + lrow) * AROWB + (lmat >> 1) * 16);
    const uint32_t boff = smem_u32 + SM_A_BYTES +
                          (uint32_t)(((lmat & 1) * 8 + lrow) * BROWB + (wn * 32 + (lmat >> 1) * 8) * 2);

    float acc[4][4][4];
    #pragma unroll
    for (int mt = 0; mt < 4; mt++)
        #pragma unroll
        for (int nt = 0; nt < 4; nt++)
            #pragma unroll
            for (int r = 0; r < 4; r++) acc[mt][nt][r] = 0.f;

    const int KT = K >> 4;
    StageRegs sr;
    ldg_tile<TERMS>(A, Bh, Bl, bm, bn, 0, K, N, tid, sr);
    sts_tile<TERMS>(smc, 0, tid, sr);
    __syncthreads();

    for (int kt = 0; kt < KT; kt++) {
        const int p = kt & 1;
        const bool more = (kt + 1 < KT);
        if (more) ldg_tile<TERMS>(A, Bh, Bl, bm, bn, (kt + 1) << 4, K, N, tid, sr);

        const uint32_t aB = aoff + p * A_TILE_B;
        const uint32_t bB = boff + p * (2 * B_TILE_B);
        uint32_t aH[4][4];
        #pragma unroll
        for (int mt = 0; mt < 4; mt++)
            LDSM4(aH[mt][0], aH[mt][1], aH[mt][2], aH[mt][3], aB + mt * (16 * AROWB));
        #pragma unroll
        for (int ntp = 0; ntp < 2; ntp++) {
            uint32_t bh[4];
            LDSM4T(bh[0], bh[1], bh[2], bh[3], bB + ntp * 32);
            if (TERMS == 2) {
                uint32_t bl[4];
                LDSM4T(bl[0], bl[1], bl[2], bl[3], bB + ntp * 32 + B_TILE_B);
                #pragma unroll
                for (int w = 0; w < 2; w++) {
                    const int nt = 2 * ntp + w;
                    #pragma unroll
                    for (int mt = 0; mt < 4; mt++) {
                        MMA_F16(acc[mt][nt], aH[mt], bl[2 * w], bl[2 * w + 1]);
                        MMA_F16(acc[mt][nt], aH[mt], bh[2 * w], bh[2 * w + 1]);
                    }
                }
            } else {
                #pragma unroll
                for (int w = 0; w < 2; w++) {
                    const int nt = 2 * ntp + w;
                    #pragma unroll
                    for (int mt = 0; mt < 4; mt++)
                        MMA_F16(acc[mt][nt], aH[mt], bh[2 * w], bh[2 * w + 1]);
                }
            }
        }
        if (more) sts_tile<TERMS>(smc, p ^ 1, tid, sr);
        __syncthreads();
    }

    // epilogue
    #pragma unroll
    for (int mt = 0; mt < 4; mt++) {
        const int m0 = bm + wm * 64 + mt * 16 + g;
        #pragma unroll
        for (int nt = 0; nt < 4; nt++) {
            const int n0 = bn + wn * 32 + nt * 8 + kq * 2;
            const float b0 = (EPI == 2) ? 0.f : bias[n0];
            const float b1 = (EPI == 2) ? 0.f : bias[n0 + 1];
            if (EPI == 0) {
                float v0 = gelu_exact(acc[mt][nt][0] + b0);
                float v1 = gelu_exact(acc[mt][nt][1] + b1);
                float v2 = gelu_exact(acc[mt][nt][2] + b0);
                float v3 = gelu_exact(acc[mt][nt][3] + b1);
                __half2 p01 = __floats2half2_rn(v0, v1);
                __half2 p23 = __floats2half2_rn(v2, v3);
                size_t i0 = ((size_t)m0 * N + n0) >> 1;
                size_t i1 = ((size_t)(m0 + 8) * N + n0) >> 1;
                ((__half2*)Ch)[i0] = p01;
                ((__half2*)Ch)[i1] = p23;
            } else if (EPI == 1) {
                float2* p0 = (float2*)&Cf[(size_t)m0 * N + n0];
                float2* p1 = (float2*)&Cf[(size_t)(m0 + 8) * N + n0];
                float2 o0 = *p0, o1 = *p1;
                o0.x += acc[mt][nt][0] + b0;
                o0.y += acc[mt][nt][1] + b1;
                o1.x += acc[mt][nt][2] + b0;
                o1.y += acc[mt][nt][3] + b1;
                *p0 = o0;
                *p1 = o1;
            } else {
                *(float2*)&Cf[(size_t)m0 * N + n0] = make_float2(acc[mt][nt][0], acc[mt][nt][1]);
                *(float2*)&Cf[(size_t)(m0 + 8) * N + n0] = make_float2(acc[mt][nt][2], acc[mt][nt][3]);
            }
        }
    }
}

__global__ void __launch_bounds__(256, 2) gemm1_f16(const float* __restrict__ b1, int l) {
    gemm_f16<0, 2>(g_s2, g_w1h + (size_t)l * DD * HH, g_w1l + (size_t)l * DD * HH,
                   b1, nullptr, g_act, NTOK, HH, DD);
}
__global__ void __launch_bounds__(256, 2) gemm2_f16(const float* __restrict__ b2, int l) {
    gemm_f16<1, 1>(g_act, g_w2h + (size_t)l * DD * HH, nullptr,
                   b2, g_h, nullptr, NTOK, DD, HH);
}
__global__ void __launch_bounds__(256, 2) gemm_out_f16(float* __restrict__ out) {
    gemm_f16<2, 2>(g_hq, g_eth, g_etl, nullptr, out, nullptr, NTOK, VV, DD);
}

// ---------------- launcher ----------------
extern "C" void kernel_launch(void* const* d_in, const int* in_sizes, int n_in,
                              void* d_out, int out_size) {
    const int*   x     = (const int*)d_in[0];
    const float* embed = (const float*)d_in[1];
    const float* kpar  = (const float*)d_in[2];
    const float* gamma = (const float*)d_in[3];
    const float* beta  = (const float*)d_in[4];
    const float* W1    = (const float*)d_in[5];
    const float* b1    = (const float*)d_in[6];
    const float* W2    = (const float*)d_in[7];
    const float* b2    = (const float*)d_in[8];
    float* out = (float*)d_out;

    cudaFuncSetAttribute(gemm1_f16, cudaFuncAttributeMaxDynamicSharedMemorySize, GSMEM);
    cudaFuncSetAttribute(gemm2_f16, cudaFuncAttributeMaxDynamicSharedMemorySize, GSMEM);
    cudaFuncSetAttribute(gemm_out_f16, cudaFuncAttributeMaxDynamicSharedMemorySize, GSMEM);
    cudaFuncSetAttribute(mag_ln_kernel, cudaFuncAttributeMaxDynamicSharedMemorySize, MLN_SMEM);

    dim3 sg(BB, NCH);

    embed_cumprod_kernel<<<NTOK / 8, 256>>>(x, embed);
    split_weights_kernel<<<(3 * DD * HH) / 256, 256>>>(W1, W2);
    embedT_split_kernel<<<dim3(VV / 32, DD / 32), dim3(32, 8)>>>(embed);
    boundA_kernel<<<sg, DD>>>();
    boundB_kernel<<<BB, DD>>>();
    boundC_kernel<<<sg, DD>>>();

    for (int l = 0; l < 3; l++) {
        scanA_kernel<<<sg, DD>>>(kpar, l);
        scanB_kernel<<<BB, DD>>>(kpar, l);
        mag_ln_kernel<<<sg, DD, MLN_SMEM>>>(kpar, l, gamma + l * DD, beta + l * DD);
        gemm1_f16<<<dim3(HH / 128, NTOK / 128), 256, GSMEM>>>(b1 + l * HH, l);
        gemm2_f16<<<dim3(DD / 128, NTOK / 128), 256, GSMEM>>>(b2 + l * DD, l);
    }
    h2half_kernel<<<(NTOK * DD) / 256, 256>>>();
    gemm_out_f16<<<dim3(VV / 128, NTOK / 128), 256, GSMEM>>>(out);
}

// round 14
// speedup vs baseline: 1.9468x; 1.0489x over previous
#include <cuda_runtime.h>
#include <cuda_fp16.h>
#include <math.h>
#include <stdint.h>

#define BB 4
#define TT 2048
#define DD 512
#define HH 2048
#define VV 256
#define NTOK (BB*TT)   // 8192
#define CS 64
#define NCH (TT/CS)

// ---------------- scratch ----------------
__device__ __align__(128) float g_h[NTOK*DD];
__device__ __align__(128) float g_s1[NTOK*DD];
__device__ __align__(128) float g_partA[BB*NCH*DD];
__device__ __align__(128) float g_partB[BB*NCH*DD];
__device__ __align__(128) __half g_s2[NTOK*DD];                 // LN out, fp16
__device__ __align__(128) __half g_act[(size_t)NTOK*HH];        // GELU out, fp16
__device__ __align__(128) __half g_hq[NTOK*DD];                 // final h, fp16
__device__ __align__(128) __half g_w1h[3*DD*HH];
__device__ __align__(128) __half g_w1l[3*DD*HH];
__device__ __align__(128) __half g_w2h[3*DD*HH];
__device__ __align__(128) __half g_eth[DD*VV];                  // embed^T hi
__device__ __align__(128) __half g_etl[DD*VV];                  // embed^T lo

__device__ __forceinline__ float softplus_lambda(float kv) {
    float sp = (kv > 0.f) ? (kv + log1pf(expf(-kv))) : log1pf(expf(kv));
    return expf(-sp);
}

// ---------------- weight split prepass (W1 hi/lo fp16; W2 hi only) ---------
__global__ void split_weights_kernel(const float* __restrict__ W1, const float* __restrict__ W2) {
    size_t i = (size_t)blockIdx.x * blockDim.x + threadIdx.x;
    float v1 = W1[i];
    __half h1 = __float2half(v1);
    g_w1h[i] = h1;
    g_w1l[i] = __float2half(v1 - __half2float(h1));
    g_w2h[i] = __float2half(W2[i]);
}

// ---------------- embed^T split prepass: E[VV][DD] -> embT[DD][VV] hi/lo ---
__global__ void embedT_split_kernel(const float* __restrict__ E) {
    __shared__ float t[32][33];
    int v0 = blockIdx.x * 32, d0 = blockIdx.y * 32;
    #pragma unroll
    for (int i = threadIdx.y; i < 32; i += 8)
        t[i][threadIdx.x] = E[(size_t)(v0 + i) * DD + d0 + threadIdx.x];
    __syncthreads();
    #pragma unroll
    for (int i = threadIdx.y; i < 32; i += 8) {
        float val = t[threadIdx.x][i];
        size_t idx = (size_t)(d0 + i) * VV + v0 + threadIdx.x;
        __half hh = __float2half(val);
        g_eth[idx] = hh;
        g_etl[idx] = __float2half(val - __half2float(hh));
    }
}

// ---------------- fused embed gather + tanh(cumprod) (warp per token) ------
__global__ void embed_cumprod_kernel(const int* __restrict__ x, const float* __restrict__ embed) {
    int w = threadIdx.x >> 5;
    int lane = threadIdx.x & 31;
    int tok = blockIdx.x * 8 + w;
    const float* src = embed + (size_t)x[tok] * DD;
    size_t base = (size_t)tok * DD + lane * 16;
    float v[16];
    #pragma unroll
    for (int j = 0; j < 4; j++)
        *(float4*)&v[j * 4] = *(const float4*)(src + lane * 16 + j * 4);
    float c[16];
    float run = 1.f;
    #pragma unroll
    for (int j = 0; j < 16; j++) {
        run *= v[j];
        c[j] = run;
    }
    float incl = run;
    #pragma unroll
    for (int off = 1; off < 32; off <<= 1) {
        float p = __shfl_up_sync(0xffffffffu, incl, off);
        if (lane >= off) incl *= p;
    }
    float pre = __shfl_up_sync(0xffffffffu, incl, 1);
    if (lane == 0) pre = 1.f;
    #pragma unroll
    for (int j = 0; j < 4; j++) {
        *(float4*)&g_h[base + j * 4] = *(const float4*)&v[j * 4];
        float4 o;
        o.x = tanhf(pre * c[j * 4 + 0]);
        o.y = tanhf(pre * c[j * 4 + 1]);
        o.z = tanhf(pre * c[j * 4 + 2]);
        o.w = tanhf(pre * c[j * 4 + 3]);
        *(float4*)&g_s1[base + j * 4] = o;
    }
}

// ============= boundary scan ================================================
__global__ void boundA_kernel() {
    int b = blockIdx.x, ch = blockIdx.y, d = threadIdx.x;
    size_t base = ((size_t)b * TT + ch * CS) * DD + d;
    float s = 0.f;
    #pragma unroll 8
    for (int i = 0; i < CS; i++) s += g_s1[base + (size_t)i * DD];
    g_partA[((size_t)b * NCH + ch) * DD + d] = s;
}

__global__ void boundB_kernel() {
    int b = blockIdx.x, d = threadIdx.x;
    float c = 0.f;
    for (int ch = 0; ch < NCH; ch++) {
        size_t idx = ((size_t)b * NCH + ch) * DD + d;
        float v = g_partA[idx];
        g_partA[idx] = c;
        c += v;
    }
}

__global__ void boundC_kernel() {
    int b = blockIdx.x, ch = blockIdx.y, d = threadIdx.x;
    size_t base = ((size_t)b * TT + ch * CS) * DD + d;
    float acc = g_partA[((size_t)b * NCH + ch) * DD + d];
    #pragma unroll 4
    for (int i = 0; i < CS; i++) {
        size_t idx = base + (size_t)i * DD;
        acc += g_s1[idx];
        g_h[idx] = g_h[idx] * (1.0f + acc);
    }
}

// ============= per-layer scans =============================================
__global__ void scanA_kernel(const float* __restrict__ kpar, int l) {
    int b = blockIdx.x, ch = blockIdx.y, d = threadIdx.x;
    float lam = softplus_lambda(kpar[l]);
    size_t base = ((size_t)b * TT + ch * CS) * DD + d;
    float s = 0.f, loc = 0.f;
    #pragma unroll 4
    for (int i = 0; i < CS; i++) {
        float v = g_h[base + (size_t)i * DD];
        s += v;
        loc = v + lam * loc;
    }
    size_t pidx = ((size_t)b * NCH + ch) * DD + d;
    g_partA[pidx] = s;
    g_partB[pidx] = loc;
}

__global__ void scanB_kernel(const float* __restrict__ kpar, int l) {
    int b = blockIdx.x, d = threadIdx.x;
    float lam = softplus_lambda(kpar[l]);
    float lamCS = powf(lam, (float)CS);
    float c1 = 0.f, c2 = 0.f;
    for (int ch = 0; ch < NCH; ch++) {
        size_t idx = ((size_t)b * NCH + ch) * DD + d;
        float a = g_partA[idx];
        float v = g_partB[idx];
        g_partA[idx] = c1;
        g_partB[idx] = c2;
        c1 += a;
        c2 = v + lamCS * c2;
    }
}

// ======== fused mag + decay-ctx + layernorm -> fp16 s2 =====================
#define MLN_SMEM ((CS*DD + 3*CS*17 + 3*CS) * 4)

__global__ void __launch_bounds__(DD, 1) mag_ln_kernel(const float* __restrict__ kpar, int l,
                                                       const float* __restrict__ gamma,
                                                       const float* __restrict__ beta) {
    extern __shared__ float sm[];
    float* sS  = sm;
    float* aM  = sS + CS * DD;
    float* a1  = aM + CS * 17;
    float* a2  = a1 + CS * 17;
    float* smu = a2 + CS * 17;
    float* srs = smu + CS;
    float* smg = srs + CS;

    int b = blockIdx.x, ch = blockIdx.y;
    int d = threadIdx.x;
    int lane = d & 31, wd = d >> 5;
    int t0 = ch * CS;
    size_t base = ((size_t)b * TT + t0) * DD + d;
    float lam = softplus_lambda(kpar[l]);
    float acc = g_partA[((size_t)b * NCH + ch) * DD + d];
    float S = g_partB[((size_t)b * NCH + ch) * DD + d];
    float hp = (t0 > 0) ? g_h[base - DD] : 0.f;

    #pragma unroll 4
    for (int i = 0; i < CS; i++) {
        float v = g_h[base + (size_t)i * DD];
        acc += v;
        float diff = acc - hp;
        float sq = diff * diff;
        S = v + lam * S;
        sS[i * DD + d] = S;
        float u1 = fabsf(S);
        float u2 = S * S;
        #pragma unroll
        for (int o = 16; o; o >>= 1) {
            sq += __shfl_down_sync(0xffffffffu, sq, o);
            u1 += __shfl_down_sync(0xffffffffu, u1, o);
            u2 += __shfl_down_sync(0xffffffffu, u2, o);
        }
        if (lane == 0) {
            aM[i * 17 + wd] = sq;
            a1[i * 17 + wd] = u1;
            a2[i * 17 + wd] = u2;
        }
        hp = v;
    }
    __syncthreads();
    if (d < CS) {
        float sm_ = 0.f, s1_ = 0.f, s2_ = 0.f;
        #pragma unroll
        for (int w = 0; w < 16; w++) {
            sm_ += aM[d * 17 + w];
            s1_ += a1[d * 17 + w];
            s2_ += a2[d * 17 + w];
        }
        float mag = sqrtf(sm_);
        float mu = mag * s1_ * (1.0f / DD);
        float ex2 = mag * mag * s2_ * (1.0f / DD);
        float var = ex2 - mu * mu;
        smu[d] = mu;
        srs[d] = rsqrtf(var + 1e-3f);
        smg[d] = mag;
    }
    __syncthreads();
    float gm = gamma[d], bt = beta[d];
    #pragma unroll 4
    for (int i = 0; i < CS; i++) {
        float ctx = smg[i] * fabsf(sS[i * DD + d]);
        float y = (ctx - smu[i]) * srs[i] * gm + bt;
        g_s2[base + (size_t)i * DD] = __float2half(y);
    }
}

// ============ fp16 tensor-core GEMM, K32 stages (2 x K16 sub-tiles) ========
// 128x128 block tile, 8 warps (2m x 4n), register staging, double-buffered,
// 2 CTAs/SM.  TERMS=2: B hi+lo; TERMS=1: B hi only.
// EPI 0: bias+GELU -> fp16 Ch.  EPI 1: bias+accum into Cf (+opt fp16 Ch).
// EPI 2: plain store to Cf.
#define AROWB 48
#define A_TILE_B (128*AROWB)           // 6144 per K16
#define BROWB 272
#define B_TILE_B (16*BROWB)            // 4352 per K16
#define KSUB 2
#define A_STAGE (KSUB*A_TILE_B)        // 12288
#define B_STAGE (KSUB*2*B_TILE_B)      // 17408
#define SM_A_BYTES (2*A_STAGE)         // 24576
#define SM_B_BYTES (2*B_STAGE)         // 34816
#define GSMEM (SM_A_BYTES + SM_B_BYTES)  // 59392

#define LDSM4(r0,r1,r2,r3,addr) \
    asm volatile("ldmatrix.sync.aligned.m8n8.x4.shared.b16 {%0,%1,%2,%3},[%4];" \
                 : "=r"(r0),"=r"(r1),"=r"(r2),"=r"(r3) : "r"(addr))
#define LDSM4T(r0,r1,r2,r3,addr) \
    asm volatile("ldmatrix.sync.aligned.m8n8.x4.trans.shared.b16 {%0,%1,%2,%3},[%4];" \
                 : "=r"(r0),"=r"(r1),"=r"(r2),"=r"(r3) : "r"(addr))
#define MMA_F16(c,a,b0,b1) \
    asm volatile("mma.sync.aligned.m16n8k16.row.col.f32.f16.f16.f32 " \
                 "{%0,%1,%2,%3},{%4,%5,%6,%7},{%8,%9},{%0,%1,%2,%3};" \
                 : "+f"(c[0]),"+f"(c[1]),"+f"(c[2]),"+f"(c[3]) \
                 : "r"(a[0]),"r"(a[1]),"r"(a[2]),"r"(a[3]),"r"(b0),"r"(b1))

struct StageRegs2 { uint4 ah[KSUB], bh[KSUB], bl[KSUB]; };

template <int TERMS>
__device__ __forceinline__ void ldg_tile(const __half* __restrict__ A,
                                         const __half* __restrict__ Bh,
                                         const __half* __restrict__ Bl,
                                         int bm, int bn, int k0, int K, int N,
                                         int tid, StageRegs2& r) {
    int arow = tid >> 1, aseg = tid & 1;
    int k = tid >> 4, ng = tid & 15;
    #pragma unroll
    for (int s = 0; s < KSUB; s++) {
        int ks = k0 + s * 16;
        r.ah[s] = *(const uint4*)(A + (size_t)(bm + arow) * K + ks + aseg * 8);
        size_t bbase = (size_t)(ks + k) * N + bn + ng * 8;
        r.bh[s] = *(const uint4*)(Bh + bbase);
        if (TERMS == 2) r.bl[s] = *(const uint4*)(Bl + bbase);
    }
}

template <int TERMS>
__device__ __forceinline__ void sts_tile(char* sbase, int p, int tid, const StageRegs2& r) {
    int arow = tid >> 1, aseg = tid & 1;
    int k = tid >> 4, ng = tid & 15;
    #pragma unroll
    for (int s = 0; s < KSUB; s++) {
        *(uint4*)(sbase + p * A_STAGE + s * A_TILE_B + arow * AROWB + aseg * 16) = r.ah[s];
        char* Bp = sbase + SM_A_BYTES + p * B_STAGE + s * (2 * B_TILE_B);
        *(uint4*)(Bp + k * BROWB + ng * 16) = r.bh[s];
        if (TERMS == 2) *(uint4*)(Bp + B_TILE_B + k * BROWB + ng * 16) = r.bl[s];
    }
}

__device__ __forceinline__ float gelu_exact(float c) {
    return 0.5f * c * (1.0f + erff(c * 0.70710678118654752f));
}

template <int EPI, int TERMS>
__device__ __forceinline__ void gemm_f16(const __half* __restrict__ A,
                                         const __half* __restrict__ Bh,
                                         const __half* __restrict__ Bl,
                                         const float* __restrict__ bias,
                                         float* __restrict__ Cf,
                                         __half* __restrict__ Ch,
                                         int M, int N, int K, int emit_half) {
    extern __shared__ char smc[];
    const int bm = blockIdx.y * 128;
    const int bn = blockIdx.x * 128;
    const int tid = threadIdx.x;
    const int lane = tid & 31;
    const int wid = tid >> 5;
    const int wm = wid >> 2, wn = wid & 3;
    const int g = lane >> 2, kq = lane & 3;
    const int lrow = lane & 7, lmat = lane >> 3;

    const uint32_t smem_u32 = (uint32_t)__cvta_generic_to_shared(smc);
    const uint32_t aoff = smem_u32 + (uint32_t)((wm * 64 + (lmat & 1) * 8 + lrow) * AROWB + (lmat >> 1) * 16);
    const uint32_t boff = smem_u32 + SM_A_BYTES +
                          (uint32_t)(((lmat & 1) * 8 + lrow) * BROWB + (wn * 32 + (lmat >> 1) * 8) * 2);

    float acc[4][4][4];
    #pragma unroll
    for (int mt = 0; mt < 4; mt++)
        #pragma unroll
        for (int nt = 0; nt < 4; nt++)
            #pragma unroll
            for (int r = 0; r < 4; r++) acc[mt][nt][r] = 0.f;

    const int KT = K >> 5;             // K32 stages
    StageRegs2 sr;
    ldg_tile<TERMS>(A, Bh, Bl, bm, bn, 0, K, N, tid, sr);
    sts_tile<TERMS>(smc, 0, tid, sr);
    __syncthreads();

    for (int kt = 0; kt < KT; kt++) {
        const int p = kt & 1;
        const bool more = (kt + 1 < KT);
        if (more) ldg_tile<TERMS>(A, Bh, Bl, bm, bn, (kt + 1) << 5, K, N, tid, sr);

        #pragma unroll
        for (int s = 0; s < KSUB; s++) {
            const uint32_t aB = aoff + p * A_STAGE + s * A_TILE_B;
            const uint32_t bB = boff + p * B_STAGE + s * (2 * B_TILE_B);
            uint32_t aH[4][4];
            #pragma unroll
            for (int mt = 0; mt < 4; mt++)
                LDSM4(aH[mt][0], aH[mt][1], aH[mt][2], aH[mt][3], aB + mt * (16 * AROWB));
            #pragma unroll
            for (int ntp = 0; ntp < 2; ntp++) {
                uint32_t bh[4];
                LDSM4T(bh[0], bh[1], bh[2], bh[3], bB + ntp * 32);
                if (TERMS == 2) {
                    uint32_t bl[4];
                    LDSM4T(bl[0], bl[1], bl[2], bl[3], bB + ntp * 32 + B_TILE_B);
                    #pragma unroll
                    for (int w = 0; w < 2; w++) {
                        const int nt = 2 * ntp + w;
                        #pragma unroll
                        for (int mt = 0; mt < 4; mt++) {
                            MMA_F16(acc[mt][nt], aH[mt], bl[2 * w], bl[2 * w + 1]);
                            MMA_F16(acc[mt][nt], aH[mt], bh[2 * w], bh[2 * w + 1]);
                        }
                    }
                } else {
                    #pragma unroll
                    for (int w = 0; w < 2; w++) {
                        const int nt = 2 * ntp + w;
                        #pragma unroll
                        for (int mt = 0; mt < 4; mt++)
                            MMA_F16(acc[mt][nt], aH[mt], bh[2 * w], bh[2 * w + 1]);
                    }
                }
            }
        }
        if (more) sts_tile<TERMS>(smc, p ^ 1, tid, sr);
        __syncthreads();
    }

    // epilogue
    #pragma unroll
    for (int mt = 0; mt < 4; mt++) {
        const int m0 = bm + wm * 64 + mt * 16 + g;
        #pragma unroll
        for (int nt = 0; nt < 4; nt++) {
            const int n0 = bn + wn * 32 + nt * 8 + kq * 2;
            const float b0 = (EPI == 2) ? 0.f : bias[n0];
            const float b1 = (EPI == 2) ? 0.f : bias[n0 + 1];
            if (EPI == 0) {
                float v0 = gelu_exact(acc[mt][nt][0] + b0);
                float v1 = gelu_exact(acc[mt][nt][1] + b1);
                float v2 = gelu_exact(acc[mt][nt][2] + b0);
                float v3 = gelu_exact(acc[mt][nt][3] + b1);
                __half2 p01 = __floats2half2_rn(v0, v1);
                __half2 p23 = __floats2half2_rn(v2, v3);
                size_t i0 = ((size_t)m0 * N + n0) >> 1;
                size_t i1 = ((size_t)(m0 + 8) * N + n0) >> 1;
                ((__half2*)Ch)[i0] = p01;
                ((__half2*)Ch)[i1] = p23;
            } else if (EPI == 1) {
                float2* p0 = (float2*)&Cf[(size_t)m0 * N + n0];
                float2* p1 = (float2*)&Cf[(size_t)(m0 + 8) * N + n0];
                float2 o0 = *p0, o1 = *p1;
                o0.x += acc[mt][nt][0] + b0;
                o0.y += acc[mt][nt][1] + b1;
                o1.x += acc[mt][nt][2] + b0;
                o1.y += acc[mt][nt][3] + b1;
                *p0 = o0;
                *p1 = o1;
                if (emit_half) {
                    size_t i0 = ((size_t)m0 * N + n0) >> 1;
                    size_t i1 = ((size_t)(m0 + 8) * N + n0) >> 1;
                    ((__half2*)Ch)[i0] = __floats2half2_rn(o0.x, o0.y);
                    ((__half2*)Ch)[i1] = __floats2half2_rn(o1.x, o1.y);
                }
            } else {
                *(float2*)&Cf[(size_t)m0 * N + n0] = make_float2(acc[mt][nt][0], acc[mt][nt][1]);
                *(float2*)&Cf[(size_t)(m0 + 8) * N + n0] = make_float2(acc[mt][nt][2], acc[mt][nt][3]);
            }
        }
    }
}

__global__ void __launch_bounds__(256, 2) gemm1_f16(const float* __restrict__ b1, int l) {
    gemm_f16<0, 2>(g_s2, g_w1h + (size_t)l * DD * HH, g_w1l + (size_t)l * DD * HH,
                   b1, nullptr, g_act, NTOK, HH, DD, 0);
}
__global__ void __launch_bounds__(256, 2) gemm2_f16(const float* __restrict__ b2, int l) {
    gemm_f16<1, 1>(g_act, g_w2h + (size_t)l * DD * HH, nullptr,
                   b2, g_h, g_hq, NTOK, DD, HH, l == 2 ? 1 : 0);
}
__global__ void __launch_bounds__(256, 2) gemm_out_f16(float* __restrict__ out) {
    gemm_f16<2, 2>(g_hq, g_eth, g_etl, nullptr, out, nullptr, NTOK, VV, DD, 0);
}

// ---------------- launcher ----------------
extern "C" void kernel_launch(void* const* d_in, const int* in_sizes, int n_in,
                              void* d_out, int out_size) {
    const int*   x     = (const int*)d_in[0];
    const float* embed = (const float*)d_in[1];
    const float* kpar  = (const float*)d_in[2];
    const float* gamma = (const float*)d_in[3];
    const float* beta  = (const float*)d_in[4];
    const float* W1    = (const float*)d_in[5];
    const float* b1    = (const float*)d_in[6];
    const float* W2    = (const float*)d_in[7];
    const float* b2    = (const float*)d_in[8];
    float* out = (float*)d_out;

    cudaFuncSetAttribute(gemm1_f16, cudaFuncAttributeMaxDynamicSharedMemorySize, GSMEM);
    cudaFuncSetAttribute(gemm2_f16, cudaFuncAttributeMaxDynamicSharedMemorySize, GSMEM);
    cudaFuncSetAttribute(gemm_out_f16, cudaFuncAttributeMaxDynamicSharedMemorySize, GSMEM);
    cudaFuncSetAttribute(mag_ln_kernel, cudaFuncAttributeMaxDynamicSharedMemorySize, MLN_SMEM);

    dim3 sg(BB, NCH);

    embed_cumprod_kernel<<<NTOK / 8, 256>>>(x, embed);
    split_weights_kernel<<<(3 * DD * HH) / 256, 256>>>(W1, W2);
    embedT_split_kernel<<<dim3(VV / 32, DD / 32), dim3(32, 8)>>>(embed);
    boundA_kernel<<<sg, DD>>>();
    boundB_kernel<<<BB, DD>>>();
    boundC_kernel<<<sg, DD>>>();

    for (int l = 0; l < 3; l++) {
        scanA_kernel<<<sg, DD>>>(kpar, l);
        scanB_kernel<<<BB, DD>>>(kpar, l);
        mag_ln_kernel<<<sg, DD, MLN_SMEM>>>(kpar, l, gamma + l * DD, beta + l * DD);
        gemm1_f16<<<dim3(HH / 128, NTOK / 128), 256, GSMEM>>>(b1 + l * HH, l);
        gemm2_f16<<<dim3(DD / 128, NTOK / 128), 256, GSMEM>>>(b2 + l * DD, l);
    }
    gemm_out_f16<<<dim3(VV / 128, NTOK / 128), 256, GSMEM>>>(out);
}

// round 15
// speedup vs baseline: 2.2432x; 1.1523x over previous
#include <cuda_runtime.h>
#include <cuda_fp16.h>
#include <math.h>
#include <stdint.h>

#define BB 4
#define TT 2048
#define DD 512
#define HH 2048
#define VV 256
#define NTOK (BB*TT)   // 8192
#define CS 64
#define NCH (TT/CS)

// ---------------- scratch ----------------
__device__ __align__(128) float g_h[NTOK*DD];
__device__ __align__(128) float g_s1[NTOK*DD];
__device__ __align__(128) float g_partA[BB*NCH*DD];
__device__ __align__(128) float g_partB[BB*NCH*DD];
__device__ __align__(128) __half g_s2[NTOK*DD];                 // LN out, fp16
__device__ __align__(128) __half g_act[(size_t)NTOK*HH];        // GELU out, fp16
__device__ __align__(128) __half g_hq[NTOK*DD];                 // final h, fp16
__device__ __align__(128) __half g_w1h[3*DD*HH];
__device__ __align__(128) __half g_w2h[3*DD*HH];
__device__ __align__(128) __half g_eth[DD*VV];                  // embed^T hi
__device__ __align__(128) __half g_etl[DD*VV];                  // embed^T lo

__device__ __forceinline__ float softplus_lambda(float kv) {
    float sp = (kv > 0.f) ? (kv + log1pf(expf(-kv))) : log1pf(expf(kv));
    return expf(-sp);
}

// ---------------- weight prepass (both W1, W2 single fp16) -----------------
__global__ void split_weights_kernel(const float* __restrict__ W1, const float* __restrict__ W2) {
    size_t i = (size_t)blockIdx.x * blockDim.x + threadIdx.x;
    g_w1h[i] = __float2half(W1[i]);
    g_w2h[i] = __float2half(W2[i]);
}

// ---------------- embed^T split prepass: E[VV][DD] -> embT[DD][VV] hi/lo ---
__global__ void embedT_split_kernel(const float* __restrict__ E) {
    __shared__ float t[32][33];
    int v0 = blockIdx.x * 32, d0 = blockIdx.y * 32;
    #pragma unroll
    for (int i = threadIdx.y; i < 32; i += 8)
        t[i][threadIdx.x] = E[(size_t)(v0 + i) * DD + d0 + threadIdx.x];
    __syncthreads();
    #pragma unroll
    for (int i = threadIdx.y; i < 32; i += 8) {
        float val = t[threadIdx.x][i];
        size_t idx = (size_t)(d0 + i) * VV + v0 + threadIdx.x;
        __half hh = __float2half(val);
        g_eth[idx] = hh;
        g_etl[idx] = __float2half(val - __half2float(hh));
    }
}

// ---------------- fused embed gather + tanh(cumprod) (warp per token) ------
__global__ void embed_cumprod_kernel(const int* __restrict__ x, const float* __restrict__ embed) {
    int w = threadIdx.x >> 5;
    int lane = threadIdx.x & 31;
    int tok = blockIdx.x * 8 + w;
    const float* src = embed + (size_t)x[tok] * DD;
    size_t base = (size_t)tok * DD + lane * 16;
    float v[16];
    #pragma unroll
    for (int j = 0; j < 4; j++)
        *(float4*)&v[j * 4] = *(const float4*)(src + lane * 16 + j * 4);
    float c[16];
    float run = 1.f;
    #pragma unroll
    for (int j = 0; j < 16; j++) {
        run *= v[j];
        c[j] = run;
    }
    float incl = run;
    #pragma unroll
    for (int off = 1; off < 32; off <<= 1) {
        float p = __shfl_up_sync(0xffffffffu, incl, off);
        if (lane >= off) incl *= p;
    }
    float pre = __shfl_up_sync(0xffffffffu, incl, 1);
    if (lane == 0) pre = 1.f;
    #pragma unroll
    for (int j = 0; j < 4; j++) {
        *(float4*)&g_h[base + j * 4] = *(const float4*)&v[j * 4];
        float4 o;
        o.x = tanhf(pre * c[j * 4 + 0]);
        o.y = tanhf(pre * c[j * 4 + 1]);
        o.z = tanhf(pre * c[j * 4 + 2]);
        o.w = tanhf(pre * c[j * 4 + 3]);
        *(float4*)&g_s1[base + j * 4] = o;
    }
}

// ============= boundary scan ================================================
__global__ void boundA_kernel() {
    int b = blockIdx.x, ch = blockIdx.y, d = threadIdx.x;
    size_t base = ((size_t)b * TT + ch * CS) * DD + d;
    float s = 0.f;
    #pragma unroll 8
    for (int i = 0; i < CS; i++) s += g_s1[base + (size_t)i * DD];
    g_partA[((size_t)b * NCH + ch) * DD + d] = s;
}

__global__ void boundB_kernel() {
    int b = blockIdx.x, d = threadIdx.x;
    float c = 0.f;
    for (int ch = 0; ch < NCH; ch++) {
        size_t idx = ((size_t)b * NCH + ch) * DD + d;
        float v = g_partA[idx];
        g_partA[idx] = c;
        c += v;
    }
}

__global__ void boundC_kernel() {
    int b = blockIdx.x, ch = blockIdx.y, d = threadIdx.x;
    size_t base = ((size_t)b * TT + ch * CS) * DD + d;
    float acc = g_partA[((size_t)b * NCH + ch) * DD + d];
    #pragma unroll 4
    for (int i = 0; i < CS; i++) {
        size_t idx = base + (size_t)i * DD;
        acc += g_s1[idx];
        g_h[idx] = g_h[idx] * (1.0f + acc);
    }
}

// ============= per-layer scans =============================================
__global__ void scanA_kernel(const float* __restrict__ kpar, int l) {
    int b = blockIdx.x, ch = blockIdx.y, d = threadIdx.x;
    float lam = softplus_lambda(kpar[l]);
    size_t base = ((size_t)b * TT + ch * CS) * DD + d;
    float s = 0.f, loc = 0.f;
    #pragma unroll 4
    for (int i = 0; i < CS; i++) {
        float v = g_h[base + (size_t)i * DD];
        s += v;
        loc = v + lam * loc;
    }
    size_t pidx = ((size_t)b * NCH + ch) * DD + d;
    g_partA[pidx] = s;
    g_partB[pidx] = loc;
}

__global__ void scanB_kernel(const float* __restrict__ kpar, int l) {
    int b = blockIdx.x, d = threadIdx.x;
    float lam = softplus_lambda(kpar[l]);
    float lamCS = powf(lam, (float)CS);
    float c1 = 0.f, c2 = 0.f;
    for (int ch = 0; ch < NCH; ch++) {
        size_t idx = ((size_t)b * NCH + ch) * DD + d;
        float a = g_partA[idx];
        float v = g_partB[idx];
        g_partA[idx] = c1;
        g_partB[idx] = c2;
        c1 += a;
        c2 = v + lamCS * c2;
    }
}

// ======== fused mag + decay-ctx + layernorm -> fp16 s2 =====================
#define MLN_SMEM ((CS*DD + 3*CS*17 + 3*CS) * 4)

__global__ void __launch_bounds__(DD, 1) mag_ln_kernel(const float* __restrict__ kpar, int l,
                                                       const float* __restrict__ gamma,
                                                       const float* __restrict__ beta) {
    extern __shared__ float sm[];
    float* sS  = sm;
    float* aM  = sS + CS * DD;
    float* a1  = aM + CS * 17;
    float* a2  = a1 + CS * 17;
    float* smu = a2 + CS * 17;
    float* srs = smu + CS;
    float* smg = srs + CS;

    int b = blockIdx.x, ch = blockIdx.y;
    int d = threadIdx.x;
    int lane = d & 31, wd = d >> 5;
    int t0 = ch * CS;
    size_t base = ((size_t)b * TT + t0) * DD + d;
    float lam = softplus_lambda(kpar[l]);
    float acc = g_partA[((size_t)b * NCH + ch) * DD + d];
    float S = g_partB[((size_t)b * NCH + ch) * DD + d];
    float hp = (t0 > 0) ? g_h[base - DD] : 0.f;

    #pragma unroll 4
    for (int i = 0; i < CS; i++) {
        float v = g_h[base + (size_t)i * DD];
        acc += v;
        float diff = acc - hp;
        float sq = diff * diff;
        S = v + lam * S;
        sS[i * DD + d] = S;
        float u1 = fabsf(S);
        float u2 = S * S;
        #pragma unroll
        for (int o = 16; o; o >>= 1) {
            sq += __shfl_down_sync(0xffffffffu, sq, o);
            u1 += __shfl_down_sync(0xffffffffu, u1, o);
            u2 += __shfl_down_sync(0xffffffffu, u2, o);
        }
        if (lane == 0) {
            aM[i * 17 + wd] = sq;
            a1[i * 17 + wd] = u1;
            a2[i * 17 + wd] = u2;
        }
        hp = v;
    }
    __syncthreads();
    if (d < CS) {
        float sm_ = 0.f, s1_ = 0.f, s2_ = 0.f;
        #pragma unroll
        for (int w = 0; w < 16; w++) {
            sm_ += aM[d * 17 + w];
            s1_ += a1[d * 17 + w];
            s2_ += a2[d * 17 + w];
        }
        float mag = sqrtf(sm_);
        float mu = mag * s1_ * (1.0f / DD);
        float ex2 = mag * mag * s2_ * (1.0f / DD);
        float var = ex2 - mu * mu;
        smu[d] = mu;
        srs[d] = rsqrtf(var + 1e-3f);
        smg[d] = mag;
    }
    __syncthreads();
    float gm = gamma[d], bt = beta[d];
    #pragma unroll 4
    for (int i = 0; i < CS; i++) {
        float ctx = smg[i] * fabsf(sS[i * DD + d]);
        float y = (ctx - smu[i]) * srs[i] * gm + bt;
        g_s2[base + (size_t)i * DD] = __float2half(y);
    }
}

// ============ fp16 tensor-core GEMM, K32 stages (2 x K16 sub-tiles) ========
// 128x128 block tile, 8 warps (2m x 4n), register staging, double-buffered,
// 2 CTAs/SM.  TERMS=2: B hi+lo; TERMS=1: B hi only.
// EPI 0: bias+GELU -> fp16 Ch.  EPI 1: bias+accum into Cf (+opt fp16 Ch).
// EPI 2: plain store to Cf.
#define AROWB 48
#define A_TILE_B (128*AROWB)           // 6144 per K16
#define BROWB 272
#define B_TILE_B (16*BROWB)            // 4352 per K16
#define KSUB 2
#define A_STAGE (KSUB*A_TILE_B)        // 12288
#define B_STAGE (KSUB*2*B_TILE_B)      // 17408
#define SM_A_BYTES (2*A_STAGE)         // 24576
#define SM_B_BYTES (2*B_STAGE)         // 34816
#define GSMEM (SM_A_BYTES + SM_B_BYTES)  // 59392

#define LDSM4(r0,r1,r2,r3,addr) \
    asm volatile("ldmatrix.sync.aligned.m8n8.x4.shared.b16 {%0,%1,%2,%3},[%4];" \
                 : "=r"(r0),"=r"(r1),"=r"(r2),"=r"(r3) : "r"(addr))
#define LDSM4T(r0,r1,r2,r3,addr) \
    asm volatile("ldmatrix.sync.aligned.m8n8.x4.trans.shared.b16 {%0,%1,%2,%3},[%4];" \
                 : "=r"(r0),"=r"(r1),"=r"(r2),"=r"(r3) : "r"(addr))
#define MMA_F16(c,a,b0,b1) \
    asm volatile("mma.sync.aligned.m16n8k16.row.col.f32.f16.f16.f32 " \
                 "{%0,%1,%2,%3},{%4,%5,%6,%7},{%8,%9},{%0,%1,%2,%3};" \
                 : "+f"(c[0]),"+f"(c[1]),"+f"(c[2]),"+f"(c[3]) \
                 : "r"(a[0]),"r"(a[1]),"r"(a[2]),"r"(a[3]),"r"(b0),"r"(b1))

struct StageRegs2 { uint4 ah[KSUB], bh[KSUB], bl[KSUB]; };

template <int TERMS>
__device__ __forceinline__ void ldg_tile(const __half* __restrict__ A,
                                         const __half* __restrict__ Bh,
                                         const __half* __restrict__ Bl,
                                         int bm, int bn, int k0, int K, int N,
                                         int tid, StageRegs2& r) {
    int arow = tid >> 1, aseg = tid & 1;
    int k = tid >> 4, ng = tid & 15;
    #pragma unroll
    for (int s = 0; s < KSUB; s++) {
        int ks = k0 + s * 16;
        r.ah[s] = *(const uint4*)(A + (size_t)(bm + arow) * K + ks + aseg * 8);
        size_t bbase = (size_t)(ks + k) * N + bn + ng * 8;
        r.bh[s] = *(const uint4*)(Bh + bbase);
        if (TERMS == 2) r.bl[s] = *(const uint4*)(Bl + bbase);
    }
}

template <int TERMS>
__device__ __forceinline__ void sts_tile(char* sbase, int p, int tid, const StageRegs2& r) {
    int arow = tid >> 1, aseg = tid & 1;
    int k = tid >> 4, ng = tid & 15;
    #pragma unroll
    for (int s = 0; s < KSUB; s++) {
        *(uint4*)(sbase + p * A_STAGE + s * A_TILE_B + arow * AROWB + aseg * 16) = r.ah[s];
        char* Bp = sbase + SM_A_BYTES + p * B_STAGE + s * (2 * B_TILE_B);
        *(uint4*)(Bp + k * BROWB + ng * 16) = r.bh[s];
        if (TERMS == 2) *(uint4*)(Bp + B_TILE_B + k * BROWB + ng * 16) = r.bl[s];
    }
}

__device__ __forceinline__ float gelu_exact(float c) {
    return 0.5f * c * (1.0f + erff(c * 0.70710678118654752f));
}

template <int EPI, int TERMS>
__device__ __forceinline__ void gemm_f16(const __half* __restrict__ A,
                                         const __half* __restrict__ Bh,
                                         const __half* __restrict__ Bl,
                                         const float* __restrict__ bias,
                                         float* __restrict__ Cf,
                                         __half* __restrict__ Ch,
                                         int M, int N, int K, int emit_half) {
    extern __shared__ char smc[];
    const int bm = blockIdx.y * 128;
    const int bn = blockIdx.x * 128;
    const int tid = threadIdx.x;
    const int lane = tid & 31;
    const int wid = tid >> 5;
    const int wm = wid >> 2, wn = wid & 3;
    const int g = lane >> 2, kq = lane & 3;
    const int lrow = lane & 7, lmat = lane >> 3;

    const uint32_t smem_u32 = (uint32_t)__cvta_generic_to_shared(smc);
    const uint32_t aoff = smem_u32 + (uint32_t)((wm * 64 + (lmat & 1) * 8 + lrow) * AROWB + (lmat >> 1) * 16);
    const uint32_t boff = smem_u32 + SM_A_BYTES +
                          (uint32_t)(((lmat & 1) * 8 + lrow) * BROWB + (wn * 32 + (lmat >> 1) * 8) * 2);

    float acc[4][4][4];
    #pragma unroll
    for (int mt = 0; mt < 4; mt++)
        #pragma unroll
        for (int nt = 0; nt < 4; nt++)
            #pragma unroll
            for (int r = 0; r < 4; r++) acc[mt][nt][r] = 0.f;

    const int KT = K >> 5;             // K32 stages
    StageRegs2 sr;
    ldg_tile<TERMS>(A, Bh, Bl, bm, bn, 0, K, N, tid, sr);
    sts_tile<TERMS>(smc, 0, tid, sr);
    __syncthreads();

    for (int kt = 0; kt < KT; kt++) {
        const int p = kt & 1;
        const bool more = (kt + 1 < KT);
        if (more) ldg_tile<TERMS>(A, Bh, Bl, bm, bn, (kt + 1) << 5, K, N, tid, sr);

        #pragma unroll
        for (int s = 0; s < KSUB; s++) {
            const uint32_t aB = aoff + p * A_STAGE + s * A_TILE_B;
            const uint32_t bB = boff + p * B_STAGE + s * (2 * B_TILE_B);
            uint32_t aH[4][4];
            #pragma unroll
            for (int mt = 0; mt < 4; mt++)
                LDSM4(aH[mt][0], aH[mt][1], aH[mt][2], aH[mt][3], aB + mt * (16 * AROWB));
            #pragma unroll
            for (int ntp = 0; ntp < 2; ntp++) {
                uint32_t bh[4];
                LDSM4T(bh[0], bh[1], bh[2], bh[3], bB + ntp * 32);
                if (TERMS == 2) {
                    uint32_t bl[4];
                    LDSM4T(bl[0], bl[1], bl[2], bl[3], bB + ntp * 32 + B_TILE_B);
                    #pragma unroll
                    for (int w = 0; w < 2; w++) {
                        const int nt = 2 * ntp + w;
                        #pragma unroll
                        for (int mt = 0; mt < 4; mt++) {
                            MMA_F16(acc[mt][nt], aH[mt], bl[2 * w], bl[2 * w + 1]);
                            MMA_F16(acc[mt][nt], aH[mt], bh[2 * w], bh[2 * w + 1]);
                        }
                    }
                } else {
                    #pragma unroll
                    for (int w = 0; w < 2; w++) {
                        const int nt = 2 * ntp + w;
                        #pragma unroll
                        for (int mt = 0; mt < 4; mt++)
                            MMA_F16(acc[mt][nt], aH[mt], bh[2 * w], bh[2 * w + 1]);
                    }
                }
            }
        }
        if (more) sts_tile<TERMS>(smc, p ^ 1, tid, sr);
        __syncthreads();
    }

    // epilogue
    #pragma unroll
    for (int mt = 0; mt < 4; mt++) {
        const int m0 = bm + wm * 64 + mt * 16 + g;
        #pragma unroll
        for (int nt = 0; nt < 4; nt++) {
            const int n0 = bn + wn * 32 + nt * 8 + kq * 2;
            const float b0 = (EPI == 2) ? 0.f : bias[n0];
            const float b1 = (EPI == 2) ? 0.f : bias[n0 + 1];
            if (EPI == 0) {
                float v0 = gelu_exact(acc[mt][nt][0] + b0);
                float v1 = gelu_exact(acc[mt][nt][1] + b1);
                float v2 = gelu_exact(acc[mt][nt][2] + b0);
                float v3 = gelu_exact(acc[mt][nt][3] + b1);
                __half2 p01 = __floats2half2_rn(v0, v1);
                __half2 p23 = __floats2half2_rn(v2, v3);
                size_t i0 = ((size_t)m0 * N + n0) >> 1;
                size_t i1 = ((size_t)(m0 + 8) * N + n0) >> 1;
                ((__half2*)Ch)[i0] = p01;
                ((__half2*)Ch)[i1] = p23;
            } else if (EPI == 1) {
                float2* p0 = (float2*)&Cf[(size_t)m0 * N + n0];
                float2* p1 = (float2*)&Cf[(size_t)(m0 + 8) * N + n0];
                float2 o0 = *p0, o1 = *p1;
                o0.x += acc[mt][nt][0] + b0;
                o0.y += acc[mt][nt][1] + b1;
                o1.x += acc[mt][nt][2] + b0;
                o1.y += acc[mt][nt][3] + b1;
                *p0 = o0;
                *p1 = o1;
                if (emit_half) {
                    size_t i0 = ((size_t)m0 * N + n0) >> 1;
                    size_t i1 = ((size_t)(m0 + 8) * N + n0) >> 1;
                    ((__half2*)Ch)[i0] = __floats2half2_rn(o0.x, o0.y);
                    ((__half2*)Ch)[i1] = __floats2half2_rn(o1.x, o1.y);
                }
            } else {
                *(float2*)&Cf[(size_t)m0 * N + n0] = make_float2(acc[mt][nt][0], acc[mt][nt][1]);
                *(float2*)&Cf[(size_t)(m0 + 8) * N + n0] = make_float2(acc[mt][nt][2], acc[mt][nt][3]);
            }
        }
    }
}

__global__ void __launch_bounds__(256, 2) gemm1_f16(const float* __restrict__ b1, int l) {
    gemm_f16<0, 1>(g_s2, g_w1h + (size_t)l * DD * HH, nullptr,
                   b1, nullptr, g_act, NTOK, HH, DD, 0);
}
__global__ void __launch_bounds__(256, 2) gemm2_f16(const float* __restrict__ b2, int l) {
    gemm_f16<1, 1>(g_act, g_w2h + (size_t)l * DD * HH, nullptr,
                   b2, g_h, g_hq, NTOK, DD, HH, l == 2 ? 1 : 0);
}
__global__ void __launch_bounds__(256, 2) gemm_out_f16(float* __restrict__ out) {
    gemm_f16<2, 2>(g_hq, g_eth, g_etl, nullptr, out, nullptr, NTOK, VV, DD, 0);
}

// ---------------- launcher ----------------
extern "C" void kernel_launch(void* const* d_in, const int* in_sizes, int n_in,
                              void* d_out, int out_size) {
    const int*   x     = (const int*)d_in[0];
    const float* embed = (const float*)d_in[1];
    const float* kpar  = (const float*)d_in[2];
    const float* gamma = (const float*)d_in[3];
    const float* beta  = (const float*)d_in[4];
    const float* W1    = (const float*)d_in[5];
    const float* b1    = (const float*)d_in[6];
    const float* W2    = (const float*)d_in[7];
    const float* b2    = (const float*)d_in[8];
    float* out = (float*)d_out;

    cudaFuncSetAttribute(gemm1_f16, cudaFuncAttributeMaxDynamicSharedMemorySize, GSMEM);
    cudaFuncSetAttribute(gemm2_f16, cudaFuncAttributeMaxDynamicSharedMemorySize, GSMEM);
    cudaFuncSetAttribute(gemm_out_f16, cudaFuncAttributeMaxDynamicSharedMemorySize, GSMEM);
    cudaFuncSetAttribute(mag_ln_kernel, cudaFuncAttributeMaxDynamicSharedMemorySize, MLN_SMEM);

    dim3 sg(BB, NCH);

    embed_cumprod_kernel<<<NTOK / 8, 256>>>(x, embed);
    split_weights_kernel<<<(3 * DD * HH) / 256, 256>>>(W1, W2);
    embedT_split_kernel<<<dim3(VV / 32, DD / 32), dim3(32, 8)>>>(embed);
    boundA_kernel<<<sg, DD>>>();
    boundB_kernel<<<BB, DD>>>();
    boundC_kernel<<<sg, DD>>>();

    for (int l = 0; l < 3; l++) {
        scanA_kernel<<<sg, DD>>>(kpar, l);
        scanB_kernel<<<BB, DD>>>(kpar, l);
        mag_ln_kernel<<<sg, DD, MLN_SMEM>>>(kpar, l, gamma + l * DD, beta + l * DD);
        gemm1_f16<<<dim3(HH / 128, NTOK / 128), 256, GSMEM>>>(b1 + l * HH, l);
        gemm2_f16<<<dim3(DD / 128, NTOK / 128), 256, GSMEM>>>(b2 + l * DD, l);
    }
    gemm_out_f16<<<dim3(VV / 128, NTOK / 128), 256, GSMEM>>>(out);
}